// round 10
// baseline (speedup 1.0000x reference)
#include <cuda_runtime.h>
#include <math.h>

#define NS 716
#define DD 64
#define NSAMP 48
#define NTILE 45            // ceil(716/16)
#define FINF 3.402823466e38f

// ---- scratch (device globals; no allocation) ----
__device__ float g_emb[NS * DD];
__device__ float g_Whp[NSAMP * 360 * 128];        // pair-interleaved: [s][j/2][c][j&1]
__device__ float g_Wh1[NSAMP * NS];
__device__ float g_Wh2[NSAMP * NS];
__device__ float g_q[NSAMP * NS * DD];
__device__ float g_kt2[NSAMP * 4 * 8 * 720 * 2];  // [s][h][c2][j] float2 pairs
__device__ float g_vt2[NSAMP * 4 * 8 * 720 * 2];  // [s][h][c2][j] float2 pairs
__device__ float g_cat[NSAMP * NS * 2 * DD];
__device__ unsigned g_cmask[NTILE * NS];
__device__ float g_wa1[DD];
__device__ float g_wa2[DD];
__device__ float g_Wc[DD * DD];   // Wo @ Wp[64:,:]
__device__ float g_bc[DD];        // bo @ Wp[64:,:] + bp

// ---- packed f32x2 helpers (sm_103a) ----
__device__ __forceinline__ unsigned long long pack2(float lo, float hi) {
    unsigned long long r;
    asm("mov.b64 %0, {%1, %2};" : "=l"(r) : "f"(lo), "f"(hi));
    return r;
}
__device__ __forceinline__ void unpack2(unsigned long long v, float& lo, float& hi) {
    asm("mov.b64 {%0, %1}, %2;" : "=f"(lo), "=f"(hi) : "l"(v));
}
__device__ __forceinline__ unsigned long long ffma2(unsigned long long a,
                                                    unsigned long long b,
                                                    unsigned long long c) {
    unsigned long long d;
    asm("fma.rn.f32x2 %0, %1, %2, %3;" : "=l"(d) : "l"(a), "l"(b), "l"(c));
    return d;
}
__device__ __forceinline__ void cp_async16(unsigned sa, const void* g) {
    asm volatile("cp.async.cg.shared.global [%0], [%1], 16;" :: "r"(sa), "l"(g));
}

// ============================================================
// Kernel PRE: adjacency pack + embedding gather + weight prep + Whp pad-zero
// grid 229 x 256
// ============================================================
__global__ void pre_kernel(const int* __restrict__ adj,
                           const float* __restrict__ in_emb,
                           const float* __restrict__ out_emb,
                           const int* __restrict__ ind,
                           const int* __restrict__ outd,
                           const float* __restrict__ W,
                           const float* __restrict__ a1, const float* __restrict__ a2,
                           const float* __restrict__ Wo, const float* __restrict__ bo,
                           const float* __restrict__ Wp, const float* __restrict__ bp) {
    int b = blockIdx.x, tid = threadIdx.x;
    if (b < 135) {
        int t = b / 3;
        int j = (b % 3) * 256 + tid;
        if (j < NS) {
            unsigned w = 0;
            #pragma unroll
            for (int ti = 0; ti < 16; ti++) {
                int i = t * 16 + ti;
                if (i < NS && adj[i * NS + j] != 0) w |= (1u << ti);
            }
            g_cmask[t * NS + j] = w;
        }
    } else if (b < 180) {
        int idx = (b - 135) * 256 + tid;
        if (idx < NS * 16) {
            int n = idx >> 4;
            int c4 = (idx & 15) * 4;
            float4 a = *(const float4*)&in_emb[ind[n] * DD + c4];
            float4 bb = *(const float4*)&out_emb[outd[n] * DD + c4];
            float4 r = {a.x + bb.x, a.y + bb.y, a.z + bb.z, a.w + bb.w};
            *(float4*)&g_emb[n * DD + c4] = r;
        }
    } else if (b == 180) {
        if (tid < DD) {
            float s1 = 0.f, s2 = 0.f;
            #pragma unroll 8
            for (int c = 0; c < DD; c++) {
                float w = W[tid * DD + c];
                s1 = fmaf(w, a1[c], s1);
                s2 = fmaf(w, a2[c], s2);
            }
            g_wa1[tid] = s1; g_wa2[tid] = s2;
            float bsum = bp[tid];
            #pragma unroll 8
            for (int m = 0; m < DD; m++) bsum = fmaf(bo[m], Wp[(DD + m) * DD + tid], bsum);
            g_bc[tid] = bsum;
        }
        for (int o = tid; o < DD * DD; o += 256) {
            int k = o >> 6, c = o & 63;
            float acc = 0.f;
            #pragma unroll 8
            for (int m = 0; m < DD; m++)
                acc = fmaf(Wo[k * DD + m], Wp[(DD + m) * DD + c], acc);
            g_Wc[o] = acc;
        }
    } else {
        // zero-fill Whp for j = 716..719 (pairs 358, 359): one block per sample
        int s = b - 181;          // 0..47
        int j = 716 + (tid >> 6); // 716..719
        int c = tid & 63;
        g_Whp[(size_t)s * 360 * 128 + (j >> 1) * 128 + c * 2 + (j & 1)] = 0.f;
    }
}

// ============================================================
// Kernel B: fused projections (Whp, q, kt2, vt2) + Wh1/Wh2.
// grid (48, 23), block 256, 32 rows/block.
// ============================================================
#define BROWS 32
__global__ __launch_bounds__(256) void proj_kernel(
    const float* __restrict__ x,
    const float* __restrict__ W,  const float* __restrict__ Wq, const float* __restrict__ bq,
    const float* __restrict__ Wk, const float* __restrict__ bk,
    const float* __restrict__ Wv, const float* __restrict__ bv) {
    __shared__ float xs[BROWS][DD];
    __shared__ float ys[BROWS][DD];
    int s = blockIdx.x;
    int n0 = blockIdx.y * BROWS;
    int tid = threadIdx.x, lane = tid & 31, w = tid >> 5;

    #pragma unroll
    for (int half = 0; half < 2; half++) {
        int idx = half * 256 + tid;
        int r = idx >> 4, k4 = (idx & 15) * 4;
        int nn = min(n0 + r, NS - 1);
        float4 xv = *(const float4*)&x[(size_t)(s * NS + nn) * DD + k4];
        float4 ev = *(const float4*)&g_emb[nn * DD + k4];
        *(float4*)&xs[r][k4] = xv;
        float4 yv = {xv.x + ev.x, xv.y + ev.y, xv.z + ev.z, xv.w + ev.w};
        *(float4*)&ys[r][k4] = yv;
    }
    __syncthreads();

    // Wh1/Wh2
    {
        float wa10 = g_wa1[lane], wa11 = g_wa1[32 + lane];
        float wa20 = g_wa2[lane], wa21 = g_wa2[32 + lane];
        #pragma unroll
        for (int rr = 0; rr < 4; rr++) {
            int r = w * 4 + rr, n = n0 + r;
            float x0 = xs[r][lane], x1 = xs[r][32 + lane];
            float s1 = x0 * wa10 + x1 * wa11;
            float s2 = x0 * wa20 + x1 * wa21;
            #pragma unroll
            for (int off = 16; off; off >>= 1) {
                s1 += __shfl_xor_sync(0xffffffffu, s1, off);
                s2 += __shfl_xor_sync(0xffffffffu, s2, off);
            }
            if (lane == 0 && n < NS) {
                g_Wh1[s * NS + n] = s1;
                g_Wh2[s * NS + n] = s2;
            }
        }
    }

    int m = tid >> 6, c = tid & 63;
    const float* wp = (m == 0) ? W : (m == 1) ? Wq : (m == 2) ? Wk : Wv;
    float bias = 0.f;
    if (m == 1) bias = bq[c]; else if (m == 2) bias = bk[c]; else if (m == 3) bias = bv[c];

    float wcol[DD];
    #pragma unroll
    for (int k = 0; k < DD; k++) wcol[k] = wp[k * DD + c];

    int h = c >> 4, c2 = (c >> 1) & 7, phalf = c & 1;
    float* tp = ((m == 2) ? g_kt2 : g_vt2) +
                (size_t)(((s * 4 + h) * 8 + c2) * 720) * 2 + phalf;
    float* whp = g_Whp + (size_t)s * 360 * 128 + c * 2;

    for (int r = 0; r < BROWS; r++) {
        int n = n0 + r;
        if (n >= NS) break;
        const float* src = (m == 0) ? xs[r] : ys[r];
        float acc = bias;
        #pragma unroll
        for (int k4 = 0; k4 < DD; k4 += 4) {
            float4 sv = *(const float4*)&src[k4];
            acc = fmaf(sv.x, wcol[k4],
                  fmaf(sv.y, wcol[k4 + 1],
                  fmaf(sv.z, wcol[k4 + 2],
                  fmaf(sv.w, wcol[k4 + 3], acc))));
        }
        if (m == 0)      whp[(n >> 1) * 128 + (n & 1)] = acc;
        else if (m == 1) g_q[(size_t)(s * NS + n) * DD + c] = acc;
        else             tp[n * 2] = acc;
    }
}

// ============================================================
// Kernel D: GAT. grid (48,45), block 256. PV uses j-paired f32x2.
// ============================================================
__global__ __launch_bounds__(256) void gat_kernel() {
    __shared__ float p[16][720];
    __shared__ float red[8][16];
    __shared__ float red1[8];
    __shared__ float smax;
    __shared__ float rowsum[16];

    int s = blockIdx.x, t = blockIdx.y;
    int i0 = t * 16;
    int tid = threadIdx.x, lane = tid & 31, w = tid >> 5;
    const unsigned* __restrict__ cm = g_cmask + t * NS;
    const float* __restrict__ wh2 = g_Wh2 + s * NS;

    float wh1[16];
    #pragma unroll
    for (int ti = 0; ti < 16; ti++) {
        int i = min(i0 + ti, NS - 1);
        wh1[ti] = g_Wh1[s * NS + i];
    }

    float lm = -FINF;
    for (int j = tid; j < NS; j += 256) lm = fmaxf(lm, wh2[j]);
    #pragma unroll
    for (int off = 16; off; off >>= 1)
        lm = fmaxf(lm, __shfl_xor_sync(0xffffffffu, lm, off));
    if (lane == 0) red1[w] = lm;
    __syncthreads();
    if (tid == 0) {
        float mm = red1[0];
        #pragma unroll
        for (int ww = 1; ww < 8; ww++) mm = fmaxf(mm, red1[ww]);
        smax = mm;
    }
    __syncthreads();

    float rme[16];
    {
        float mw = smax;
        #pragma unroll
        for (int ti = 0; ti < 16; ti++) {
            float e = wh1[ti] + mw;
            rme[ti] = fmaxf(e, 0.2f * e);
        }
    }

    // main pass: exp + sum (padded to 720 with zeros)
    float lsum[16];
    #pragma unroll
    for (int ti = 0; ti < 16; ti++) lsum[ti] = 0.f;
    for (int j = tid; j < 720; j += 256) {
        bool in = j < NS;
        float w2 = in ? wh2[j] : 0.f;
        unsigned mk = in ? cm[j] : 0u;
        #pragma unroll
        for (int ti = 0; ti < 16; ti++) {
            float e = wh1[ti] + w2;
            e = fmaxf(e, 0.2f * e);
            float pe = ((mk >> ti) & 1u) ? __expf(e - rme[ti]) : 0.0f;
            p[ti][j] = pe;
            lsum[ti] += pe;
        }
    }
    #pragma unroll
    for (int ti = 0; ti < 16; ti++)
        #pragma unroll
        for (int off = 16; off; off >>= 1)
            lsum[ti] += __shfl_xor_sync(0xffffffffu, lsum[ti], off);
    if (lane == 0) {
        #pragma unroll
        for (int ti = 0; ti < 16; ti++) red[w][ti] = lsum[ti];
    }
    __syncthreads();
    if (tid < 16) {
        float ss = red[0][tid];
        #pragma unroll
        for (int ww = 1; ww < 8; ww++) ss += red[ww][tid];
        rowsum[tid] = ss;
    }
    __syncthreads();

    // PV: j-paired f32x2. Thread owns (c, g); even/odd j partial sums in lanes.
    int c = tid & 63, g = tid >> 6;
    unsigned long long acc2[16];
    #pragma unroll
    for (int ti = 0; ti < 16; ti++) acc2[ti] = 0ull;
    const unsigned long long* __restrict__ Whp2 =
        (const unsigned long long*)(g_Whp + (size_t)s * 360 * 128);
    for (int j0 = g * 8; j0 < 720; j0 += 32) {
        int pr = j0 >> 1;
        unsigned long long w0 = Whp2[(pr + 0) * 64 + c];
        unsigned long long w1 = Whp2[(pr + 1) * 64 + c];
        unsigned long long w2 = Whp2[(pr + 2) * 64 + c];
        unsigned long long w3 = Whp2[(pr + 3) * 64 + c];
        #pragma unroll
        for (int ti = 0; ti < 16; ti++) {
            ulonglong2 pa = *(const ulonglong2*)&p[ti][j0];
            ulonglong2 pb = *(const ulonglong2*)&p[ti][j0 + 4];
            acc2[ti] = ffma2(pa.x, w0, acc2[ti]);
            acc2[ti] = ffma2(pa.y, w1, acc2[ti]);
            acc2[ti] = ffma2(pb.x, w2, acc2[ti]);
            acc2[ti] = ffma2(pb.y, w3, acc2[ti]);
        }
    }
    float acc[16];
    #pragma unroll
    for (int ti = 0; ti < 16; ti++) {
        float lo, hi;
        unpack2(acc2[ti], lo, hi);
        acc[ti] = lo + hi;
    }
    __syncthreads();

    float* partial = &p[0][0];
    #pragma unroll
    for (int ti = 0; ti < 16; ti++) partial[(g * 16 + ti) * 64 + c] = acc[ti];
    __syncthreads();

    if (g == 0) {
        #pragma unroll
        for (int ti = 0; ti < 16; ti++) {
            int i = i0 + ti;
            if (i >= NS) continue;
            float v = (partial[ti * 64 + c] + partial[(16 + ti) * 64 + c] +
                       partial[(32 + ti) * 64 + c] + partial[(48 + ti) * 64 + c]) / rowsum[ti];
            v = v > 0.f ? v : expm1f(v);
            g_cat[(size_t)(s * NS + i) * 2 * DD + c] = v;
        }
    }
}

// ============================================================
// Kernel E: MHA — double-buffered cp.async k/v tiles, 4 q/warp, f32x2.
// grid (48, 45, 4), block 128 (4 warps).
// ============================================================
__global__ __launch_bounds__(128, 3) void mha_kernel() {
    __shared__ __align__(16) unsigned long long sbuf[4096];  // 2 x (k 1024 | v 1024); red overlay

    int s = blockIdx.x;
    int i0 = blockIdx.y * 16;
    int h = blockIdx.z;
    int tid = threadIdx.x, lane = tid & 31, w = tid >> 5;

    // q in registers, pre-scaled by 1/sqrt(16)
    unsigned long long qreg[4][8];
    #pragma unroll
    for (int tq = 0; tq < 4; tq++) {
        int iq = min(i0 + w * 4 + tq, NS - 1);
        const float2* qp2 = (const float2*)(g_q + (size_t)(s * NS + iq) * DD + h * 16);
        #pragma unroll
        for (int c2 = 0; c2 < 8; c2++) {
            float2 v = qp2[c2];
            qreg[tq][c2] = pack2(v.x * 0.25f, v.y * 0.25f);
        }
    }

    const float* __restrict__ ktf = g_kt2 + (size_t)(s * 4 + h) * 8 * 720 * 2;
    const float* __restrict__ vtf = g_vt2 + (size_t)(s * 4 + h) * 8 * 720 * 2;
    unsigned sbase = (unsigned)__cvta_generic_to_shared(sbuf);

    unsigned long long acc2[4][8];
    #pragma unroll
    for (int tq = 0; tq < 4; tq++)
        #pragma unroll
        for (int c2 = 0; c2 < 8; c2++) acc2[tq][c2] = 0ull;
    float l[4] = {0.f, 0.f, 0.f, 0.f};

    // prologue: async fill tile 0 into buf 0
    {
        #pragma unroll
        for (int i = 0; i < 4; i++) {
            int f = i * 128 + tid;
            int c2 = f >> 6, jp = f & 63;
            int j = jp * 2;
            if (j < NS) {
                unsigned dst = sbase + (unsigned)(c2 * 128 + jp * 2) * 8;
                cp_async16(dst, ktf + (c2 * 720 + j) * 2);
                cp_async16(dst + 1024 * 8, vtf + (c2 * 720 + j) * 2);
            }
        }
        asm volatile("cp.async.commit_group;");
    }

    for (int t = 0; t < 6; t++) {
        asm volatile("cp.async.wait_group 0;");
        __syncthreads();
        if (t < 5) {
            int jb = (t + 1) * 128;
            unsigned bufo = ((unsigned)((t + 1) & 1)) * 2048 * 8;
            #pragma unroll
            for (int i = 0; i < 4; i++) {
                int f = i * 128 + tid;
                int c2 = f >> 6, jp = f & 63;
                int j = jb + jp * 2;
                if (j < NS) {
                    unsigned dst = sbase + bufo + (unsigned)(c2 * 128 + jp * 2) * 8;
                    cp_async16(dst, ktf + (c2 * 720 + j) * 2);
                    cp_async16(dst + 1024 * 8, vtf + (c2 * 720 + j) * 2);
                }
            }
            asm volatile("cp.async.commit_group;");
        }

        const unsigned long long* ks = sbuf + (t & 1) * 2048;
        const unsigned long long* vs = ks + 1024;
        int jb = t * 128;
        #pragma unroll
        for (int sub = 0; sub < 4; sub++) {
            int jl = sub * 32 + lane;
            bool ok = (jb + jl) < NS;
            unsigned long long sco2[4] = {0ull, 0ull, 0ull, 0ull};
            #pragma unroll
            for (int c2 = 0; c2 < 8; c2++) {
                unsigned long long kv = ks[c2 * 128 + jl];
                sco2[0] = ffma2(qreg[0][c2], kv, sco2[0]);
                sco2[1] = ffma2(qreg[1][c2], kv, sco2[1]);
                sco2[2] = ffma2(qreg[2][c2], kv, sco2[2]);
                sco2[3] = ffma2(qreg[3][c2], kv, sco2[3]);
            }
            unsigned long long p2[4];
            #pragma unroll
            for (int tq = 0; tq < 4; tq++) {
                float lo, hi;
                unpack2(sco2[tq], lo, hi);
                float pe = ok ? __expf(lo + hi) : 0.0f;
                l[tq] += pe;
                p2[tq] = pack2(pe, pe);
            }
            #pragma unroll
            for (int c2 = 0; c2 < 8; c2++) {
                unsigned long long vv = vs[c2 * 128 + jl];
                acc2[0][c2] = ffma2(p2[0], vv, acc2[0][c2]);
                acc2[1][c2] = ffma2(p2[1], vv, acc2[1][c2]);
                acc2[2][c2] = ffma2(p2[2], vv, acc2[2][c2]);
                acc2[3][c2] = ffma2(p2[3], vv, acc2[3][c2]);
            }
        }
    }

    // reduce l across lanes
    #pragma unroll
    for (int tq = 0; tq < 4; tq++)
        #pragma unroll
        for (int off = 16; off; off >>= 1)
            l[tq] += __shfl_xor_sync(0xffffffffu, l[tq], off);
    float linv[4];
    #pragma unroll
    for (int tq = 0; tq < 4; tq++) linv[tq] = 1.0f / l[tq];

    __syncthreads();   // all smem tile reads done before overlay
    unsigned long long* red = sbuf + w * 528;   // [16][33] per warp
    #pragma unroll
    for (int ps = 0; ps < 2; ps++) {
        #pragma unroll
        for (int tq2 = 0; tq2 < 2; tq2++)
            #pragma unroll
            for (int c2 = 0; c2 < 8; c2++)
                red[(tq2 * 8 + c2) * 33 + lane] = acc2[ps * 2 + tq2][c2];
        __syncwarp();
        int tql = lane >> 4, cl = lane & 15;
        const float* base = (const float*)&red[(tql * 8 + (cl >> 1)) * 33];
        int hf = cl & 1;
        float v = 0.f;
        #pragma unroll
        for (int ll = 0; ll < 32; ll++) v += base[ll * 2 + hf];
        float li = linv[ps * 2 + tql];
        int i = i0 + w * 4 + ps * 2 + tql;
        if (i < NS)
            g_cat[(size_t)(s * NS + i) * 2 * DD + DD + h * 16 + cl] = v * li;
        __syncwarp();
    }
}

// ============================================================
// Kernel F: final projection, 16 rows/block, 4-way k-split.
// ============================================================
__global__ __launch_bounds__(256) void final_kernel(const float* __restrict__ Wp,
                                                    float* __restrict__ out) {
    __shared__ float cs[16][2 * DD];
    __shared__ float pa[4][16][64];
    int s = blockIdx.x;
    int n0 = blockIdx.y * 16;
    int tid = threadIdx.x;

    #pragma unroll
    for (int half = 0; half < 2; half++) {
        int idx = half * 256 + tid;
        int r = idx >> 5, k4 = (idx & 31) * 4;
        int nn = min(n0 + r, NS - 1);
        *(float4*)&cs[r][k4] = *(const float4*)&g_cat[(size_t)(s * NS + nn) * 2 * DD + k4];
    }
    __syncthreads();

    int c = tid & 63, kg = tid >> 6;
    float acc[16];
    #pragma unroll
    for (int r = 0; r < 16; r++) acc[r] = 0.f;
    for (int k0 = kg * 32; k0 < kg * 32 + 32; k0 += 4) {
        const float* wsrc = (k0 < 64) ? (Wp + k0 * DD) : (g_Wc + (k0 - 64) * DD);
        float wv0 = wsrc[c];
        float wv1 = wsrc[DD + c];
        float wv2 = wsrc[2 * DD + c];
        float wv3 = wsrc[3 * DD + c];
        #pragma unroll
        for (int r = 0; r < 16; r++) {
            float4 cv = *(const float4*)&cs[r][k0];
            acc[r] = fmaf(cv.x, wv0, fmaf(cv.y, wv1,
                     fmaf(cv.z, wv2, fmaf(cv.w, wv3, acc[r]))));
        }
    }
    #pragma unroll
    for (int r = 0; r < 16; r++) pa[kg][r][c] = acc[r];
    __syncthreads();

    if (kg == 0) {
        #pragma unroll
        for (int r = 0; r < 16; r++) {
            int n = n0 + r;
            if (n < NS)
                out[(size_t)(s * NS + n) * DD + c] =
                    pa[0][r][c] + pa[1][r][c] + pa[2][r][c] + pa[3][r][c] + g_bc[c];
        }
    }
}

// ============================================================
extern "C" void kernel_launch(void* const* d_in, const int* in_sizes, int n_in,
                              void* d_out, int out_size) {
    const float* x      = (const float*)d_in[0];
    const int*   adj    = (const int*)d_in[1];
    const int*   ind    = (const int*)d_in[2];
    const int*   outd   = (const int*)d_in[3];
    const float* in_emb = (const float*)d_in[4];
    const float* out_emb= (const float*)d_in[5];
    const float* W      = (const float*)d_in[6];
    const float* a1     = (const float*)d_in[7];
    const float* a2     = (const float*)d_in[8];
    const float* Wq     = (const float*)d_in[9];
    const float* bq     = (const float*)d_in[10];
    const float* Wk     = (const float*)d_in[11];
    const float* bk     = (const float*)d_in[12];
    const float* Wv     = (const float*)d_in[13];
    const float* bv     = (const float*)d_in[14];
    const float* Wo     = (const float*)d_in[15];
    const float* bo     = (const float*)d_in[16];
    const float* Wp     = (const float*)d_in[17];
    const float* bp     = (const float*)d_in[18];
    float* out = (float*)d_out;

    pre_kernel<<<229, 256>>>(adj, in_emb, out_emb, ind, outd, W, a1, a2, Wo, bo, Wp, bp);
    proj_kernel<<<dim3(NSAMP, (NS + BROWS - 1) / BROWS), 256>>>(x, W, Wq, bq, Wk, bk, Wv, bv);
    gat_kernel<<<dim3(NSAMP, NTILE), 256>>>();
    mha_kernel<<<dim3(NSAMP, NTILE, 4), 128>>>();
    final_kernel<<<dim3(NSAMP, NTILE), 256>>>(Wp, out);
}

// round 11
// speedup vs baseline: 1.0844x; 1.0844x over previous
#include <cuda_runtime.h>
#include <math.h>

#define NS 716
#define DD 64
#define NSAMP 48
#define NTILE 45            // ceil(716/16)
#define FINF 3.402823466e38f
#define LOG2E 1.4426950408889634f

// ---- scratch (device globals; no allocation) ----
__device__ float g_emb[NS * DD];
__device__ float g_Whp[NSAMP * 360 * 128];        // pair-interleaved: [s][j/2][c][j&1]
__device__ float g_Wh1[NSAMP * NS];               // pre-scaled by log2e
__device__ float g_Wh2[NSAMP * NS];               // pre-scaled by log2e
__device__ float g_q[NSAMP * NS * DD];
__device__ float g_kt2[NSAMP * 4 * 8 * 720 * 2];  // [s][h][c2][j] float2 pairs
__device__ float g_vt2[NSAMP * 4 * 8 * 720 * 2];  // [s][h][c2][j] float2 pairs
__device__ float g_cat[NSAMP * NS * 2 * DD];
__device__ unsigned g_cmask[NTILE * NS];
__device__ float g_wa1[DD];
__device__ float g_wa2[DD];
__device__ float g_Wc[DD * DD];   // Wo @ Wp[64:,:]
__device__ float g_bc[DD];        // bo @ Wp[64:,:] + bp

// ---- packed f32x2 helpers (sm_103a) ----
__device__ __forceinline__ unsigned long long pack2(float lo, float hi) {
    unsigned long long r;
    asm("mov.b64 %0, {%1, %2};" : "=l"(r) : "f"(lo), "f"(hi));
    return r;
}
__device__ __forceinline__ void unpack2(unsigned long long v, float& lo, float& hi) {
    asm("mov.b64 {%0, %1}, %2;" : "=f"(lo), "=f"(hi) : "l"(v));
}
__device__ __forceinline__ unsigned long long ffma2(unsigned long long a,
                                                    unsigned long long b,
                                                    unsigned long long c) {
    unsigned long long d;
    asm("fma.rn.f32x2 %0, %1, %2, %3;" : "=l"(d) : "l"(a), "l"(b), "l"(c));
    return d;
}
__device__ __forceinline__ float ex2f(float x) {
    float y;
    asm("ex2.approx.ftz.f32 %0, %1;" : "=f"(y) : "f"(x));
    return y;
}
__device__ __forceinline__ void cp_async16(unsigned sa, const void* g) {
    asm volatile("cp.async.cg.shared.global [%0], [%1], 16;" :: "r"(sa), "l"(g));
}

// ============================================================
// Kernel PRE: adjacency pack + embedding gather + weight prep + Whp pad-zero
// grid 229 x 256
// ============================================================
__global__ void pre_kernel(const int* __restrict__ adj,
                           const float* __restrict__ in_emb,
                           const float* __restrict__ out_emb,
                           const int* __restrict__ ind,
                           const int* __restrict__ outd,
                           const float* __restrict__ W,
                           const float* __restrict__ a1, const float* __restrict__ a2,
                           const float* __restrict__ Wo, const float* __restrict__ bo,
                           const float* __restrict__ Wp, const float* __restrict__ bp) {
    int b = blockIdx.x, tid = threadIdx.x;
    if (b < 135) {
        int t = b / 3;
        int j = (b % 3) * 256 + tid;
        if (j < NS) {
            unsigned w = 0;
            #pragma unroll
            for (int ti = 0; ti < 16; ti++) {
                int i = t * 16 + ti;
                if (i < NS && adj[i * NS + j] != 0) w |= (1u << ti);
            }
            g_cmask[t * NS + j] = w;
        }
    } else if (b < 180) {
        int idx = (b - 135) * 256 + tid;
        if (idx < NS * 16) {
            int n = idx >> 4;
            int c4 = (idx & 15) * 4;
            float4 a = *(const float4*)&in_emb[ind[n] * DD + c4];
            float4 bb = *(const float4*)&out_emb[outd[n] * DD + c4];
            float4 r = {a.x + bb.x, a.y + bb.y, a.z + bb.z, a.w + bb.w};
            *(float4*)&g_emb[n * DD + c4] = r;
        }
    } else if (b == 180) {
        if (tid < DD) {
            float s1 = 0.f, s2 = 0.f;
            #pragma unroll 8
            for (int c = 0; c < DD; c++) {
                float w = W[tid * DD + c];
                s1 = fmaf(w, a1[c], s1);
                s2 = fmaf(w, a2[c], s2);
            }
            // scale by log2e: LeakyReLU is positively homogeneous, so the GAT
            // softmax can run in the exp2 domain exactly.
            g_wa1[tid] = s1 * LOG2E; g_wa2[tid] = s2 * LOG2E;
            float bsum = bp[tid];
            #pragma unroll 8
            for (int m = 0; m < DD; m++) bsum = fmaf(bo[m], Wp[(DD + m) * DD + tid], bsum);
            g_bc[tid] = bsum;
        }
        for (int o = tid; o < DD * DD; o += 256) {
            int k = o >> 6, c = o & 63;
            float acc = 0.f;
            #pragma unroll 8
            for (int m = 0; m < DD; m++)
                acc = fmaf(Wo[k * DD + m], Wp[(DD + m) * DD + c], acc);
            g_Wc[o] = acc;
        }
    } else {
        int s = b - 181;          // 0..47
        int j = 716 + (tid >> 6); // 716..719
        int c = tid & 63;
        g_Whp[(size_t)s * 360 * 128 + (j >> 1) * 128 + c * 2 + (j & 1)] = 0.f;
    }
}

// ============================================================
// Kernel B: fused projections (Whp, q, kt2, vt2) + Wh1/Wh2. f32x2 inner.
// grid (48, 23), block 256, 32 rows/block.
// ============================================================
#define BROWS 32
__global__ __launch_bounds__(256) void proj_kernel(
    const float* __restrict__ x,
    const float* __restrict__ W,  const float* __restrict__ Wq, const float* __restrict__ bq,
    const float* __restrict__ Wk, const float* __restrict__ bk,
    const float* __restrict__ Wv, const float* __restrict__ bv) {
    __shared__ float xs[BROWS][DD];
    __shared__ float ys[BROWS][DD];
    int s = blockIdx.x;
    int n0 = blockIdx.y * BROWS;
    int tid = threadIdx.x, lane = tid & 31, w = tid >> 5;

    #pragma unroll
    for (int half = 0; half < 2; half++) {
        int idx = half * 256 + tid;
        int r = idx >> 4, k4 = (idx & 15) * 4;
        int nn = min(n0 + r, NS - 1);
        float4 xv = *(const float4*)&x[(size_t)(s * NS + nn) * DD + k4];
        float4 ev = *(const float4*)&g_emb[nn * DD + k4];
        *(float4*)&xs[r][k4] = xv;
        float4 yv = {xv.x + ev.x, xv.y + ev.y, xv.z + ev.z, xv.w + ev.w};
        *(float4*)&ys[r][k4] = yv;
    }
    __syncthreads();

    // Wh1/Wh2 (log2e-scaled via g_wa1/g_wa2)
    {
        float wa10 = g_wa1[lane], wa11 = g_wa1[32 + lane];
        float wa20 = g_wa2[lane], wa21 = g_wa2[32 + lane];
        #pragma unroll
        for (int rr = 0; rr < 4; rr++) {
            int r = w * 4 + rr, n = n0 + rr + w * 4;
            float x0 = xs[r][lane], x1 = xs[r][32 + lane];
            float s1 = x0 * wa10 + x1 * wa11;
            float s2 = x0 * wa20 + x1 * wa21;
            #pragma unroll
            for (int off = 16; off; off >>= 1) {
                s1 += __shfl_xor_sync(0xffffffffu, s1, off);
                s2 += __shfl_xor_sync(0xffffffffu, s2, off);
            }
            if (lane == 0 && n < NS) {
                g_Wh1[s * NS + n] = s1;
                g_Wh2[s * NS + n] = s2;
            }
        }
    }

    int m = tid >> 6, c = tid & 63;
    const float* wp = (m == 0) ? W : (m == 1) ? Wq : (m == 2) ? Wk : Wv;
    float bias = 0.f;
    if (m == 1) bias = bq[c]; else if (m == 2) bias = bk[c]; else if (m == 3) bias = bv[c];

    // weight column packed as 32 k-pairs
    unsigned long long wcol2[32];
    #pragma unroll
    for (int k2 = 0; k2 < 32; k2++)
        wcol2[k2] = pack2(wp[(2 * k2) * DD + c], wp[(2 * k2 + 1) * DD + c]);

    int h = c >> 4, c2 = (c >> 1) & 7, phalf = c & 1;
    float* tp = ((m == 2) ? g_kt2 : g_vt2) +
                (size_t)(((s * 4 + h) * 8 + c2) * 720) * 2 + phalf;
    float* whp = g_Whp + (size_t)s * 360 * 128 + c * 2;

    for (int r = 0; r < BROWS; r++) {
        int n = n0 + r;
        if (n >= NS) break;
        const float* src = (m == 0) ? xs[r] : ys[r];
        unsigned long long acc2 = pack2(bias, 0.f);
        #pragma unroll
        for (int k2 = 0; k2 < 32; k2 += 2) {
            ulonglong2 sv = *(const ulonglong2*)&src[k2 * 2];
            acc2 = ffma2(sv.x, wcol2[k2], acc2);
            acc2 = ffma2(sv.y, wcol2[k2 + 1], acc2);
        }
        float lo, hi;
        unpack2(acc2, lo, hi);
        float acc = lo + hi;
        if (m == 0)      whp[(n >> 1) * 128 + (n & 1)] = acc;
        else if (m == 1) g_q[(size_t)(s * NS + n) * DD + c] = acc;
        else             tp[n * 2] = acc;
    }
}

// ============================================================
// Kernel D: GAT. grid (48,45), block 256. exp2-domain softmax; j-paired PV.
// ============================================================
__global__ __launch_bounds__(256) void gat_kernel() {
    __shared__ float p[16][720];
    __shared__ float red[8][16];
    __shared__ float red1[8];
    __shared__ float smax;
    __shared__ float rowsum[16];

    int s = blockIdx.x, t = blockIdx.y;
    int i0 = t * 16;
    int tid = threadIdx.x, lane = tid & 31, w = tid >> 5;
    const unsigned* __restrict__ cm = g_cmask + t * NS;
    const float* __restrict__ wh2 = g_Wh2 + s * NS;

    float wh1[16];
    #pragma unroll
    for (int ti = 0; ti < 16; ti++) {
        int i = min(i0 + ti, NS - 1);
        wh1[ti] = g_Wh1[s * NS + i];
    }

    float lm = -FINF;
    for (int j = tid; j < NS; j += 256) lm = fmaxf(lm, wh2[j]);
    #pragma unroll
    for (int off = 16; off; off >>= 1)
        lm = fmaxf(lm, __shfl_xor_sync(0xffffffffu, lm, off));
    if (lane == 0) red1[w] = lm;
    __syncthreads();
    if (tid == 0) {
        float mm = red1[0];
        #pragma unroll
        for (int ww = 1; ww < 8; ww++) mm = fmaxf(mm, red1[ww]);
        smax = mm;
    }
    __syncthreads();

    float rme[16];
    {
        float mw = smax;
        #pragma unroll
        for (int ti = 0; ti < 16; ti++) {
            float e = wh1[ti] + mw;
            rme[ti] = fmaxf(e, 0.2f * e);
        }
    }

    // main pass: exp2 + sum (padded to 720 with zeros)
    float lsum[16];
    #pragma unroll
    for (int ti = 0; ti < 16; ti++) lsum[ti] = 0.f;
    for (int j = tid; j < 720; j += 256) {
        bool in = j < NS;
        float w2 = in ? wh2[j] : 0.f;
        unsigned mk = in ? cm[j] : 0u;
        #pragma unroll
        for (int ti = 0; ti < 16; ti++) {
            float e = wh1[ti] + w2;
            e = fmaxf(e, 0.2f * e);
            float pe = ((mk >> ti) & 1u) ? ex2f(e - rme[ti]) : 0.0f;
            p[ti][j] = pe;
            lsum[ti] += pe;
        }
    }
    #pragma unroll
    for (int ti = 0; ti < 16; ti++)
        #pragma unroll
        for (int off = 16; off; off >>= 1)
            lsum[ti] += __shfl_xor_sync(0xffffffffu, lsum[ti], off);
    if (lane == 0) {
        #pragma unroll
        for (int ti = 0; ti < 16; ti++) red[w][ti] = lsum[ti];
    }
    __syncthreads();
    if (tid < 16) {
        float ss = red[0][tid];
        #pragma unroll
        for (int ww = 1; ww < 8; ww++) ss += red[ww][tid];
        rowsum[tid] = ss;
    }
    __syncthreads();

    // PV: j-paired f32x2
    int c = tid & 63, g = tid >> 6;
    unsigned long long acc2[16];
    #pragma unroll
    for (int ti = 0; ti < 16; ti++) acc2[ti] = 0ull;
    const unsigned long long* __restrict__ Whp2 =
        (const unsigned long long*)(g_Whp + (size_t)s * 360 * 128);
    for (int j0 = g * 8; j0 < 720; j0 += 32) {
        int pr = j0 >> 1;
        unsigned long long w0 = Whp2[(pr + 0) * 64 + c];
        unsigned long long w1 = Whp2[(pr + 1) * 64 + c];
        unsigned long long w2 = Whp2[(pr + 2) * 64 + c];
        unsigned long long w3 = Whp2[(pr + 3) * 64 + c];
        #pragma unroll
        for (int ti = 0; ti < 16; ti++) {
            ulonglong2 pa = *(const ulonglong2*)&p[ti][j0];
            ulonglong2 pb = *(const ulonglong2*)&p[ti][j0 + 4];
            acc2[ti] = ffma2(pa.x, w0, acc2[ti]);
            acc2[ti] = ffma2(pa.y, w1, acc2[ti]);
            acc2[ti] = ffma2(pb.x, w2, acc2[ti]);
            acc2[ti] = ffma2(pb.y, w3, acc2[ti]);
        }
    }
    float acc[16];
    #pragma unroll
    for (int ti = 0; ti < 16; ti++) {
        float lo, hi;
        unpack2(acc2[ti], lo, hi);
        acc[ti] = lo + hi;
    }
    __syncthreads();

    float* partial = &p[0][0];
    #pragma unroll
    for (int ti = 0; ti < 16; ti++) partial[(g * 16 + ti) * 64 + c] = acc[ti];
    __syncthreads();

    if (g == 0) {
        #pragma unroll
        for (int ti = 0; ti < 16; ti++) {
            int i = i0 + ti;
            if (i >= NS) continue;
            float v = (partial[ti * 64 + c] + partial[(16 + ti) * 64 + c] +
                       partial[(32 + ti) * 64 + c] + partial[(48 + ti) * 64 + c]) / rowsum[ti];
            v = v > 0.f ? v : expm1f(v);
            g_cat[(size_t)(s * NS + i) * 2 * DD + c] = v;
        }
    }
}

// ============================================================
// Kernel E: MHA — cp.async double-buffered, 4 q/warp, f32x2, exp2 domain.
// grid (48, 45, 4), block 128 (4 warps).
// ============================================================
__global__ __launch_bounds__(128, 3) void mha_kernel() {
    __shared__ __align__(16) unsigned long long sbuf[4096];

    int s = blockIdx.x;
    int i0 = blockIdx.y * 16;
    int h = blockIdx.z;
    int tid = threadIdx.x, lane = tid & 31, w = tid >> 5;

    // q in registers, pre-scaled by log2e/sqrt(16): scores land in exp2 domain
    unsigned long long qreg[4][8];
    #pragma unroll
    for (int tq = 0; tq < 4; tq++) {
        int iq = min(i0 + w * 4 + tq, NS - 1);
        const float2* qp2 = (const float2*)(g_q + (size_t)(s * NS + iq) * DD + h * 16);
        #pragma unroll
        for (int c2 = 0; c2 < 8; c2++) {
            float2 v = qp2[c2];
            qreg[tq][c2] = pack2(v.x * (0.25f * LOG2E), v.y * (0.25f * LOG2E));
        }
    }

    const float* __restrict__ ktf = g_kt2 + (size_t)(s * 4 + h) * 8 * 720 * 2;
    const float* __restrict__ vtf = g_vt2 + (size_t)(s * 4 + h) * 8 * 720 * 2;
    unsigned sbase = (unsigned)__cvta_generic_to_shared(sbuf);

    unsigned long long acc2[4][8];
    #pragma unroll
    for (int tq = 0; tq < 4; tq++)
        #pragma unroll
        for (int c2 = 0; c2 < 8; c2++) acc2[tq][c2] = 0ull;
    float l[4] = {0.f, 0.f, 0.f, 0.f};

    {
        #pragma unroll
        for (int i = 0; i < 4; i++) {
            int f = i * 128 + tid;
            int c2 = f >> 6, jp = f & 63;
            int j = jp * 2;
            if (j < NS) {
                unsigned dst = sbase + (unsigned)(c2 * 128 + jp * 2) * 8;
                cp_async16(dst, ktf + (c2 * 720 + j) * 2);
                cp_async16(dst + 1024 * 8, vtf + (c2 * 720 + j) * 2);
            }
        }
        asm volatile("cp.async.commit_group;");
    }

    for (int t = 0; t < 6; t++) {
        asm volatile("cp.async.wait_group 0;");
        __syncthreads();
        if (t < 5) {
            int jb = (t + 1) * 128;
            unsigned bufo = ((unsigned)((t + 1) & 1)) * 2048 * 8;
            #pragma unroll
            for (int i = 0; i < 4; i++) {
                int f = i * 128 + tid;
                int c2 = f >> 6, jp = f & 63;
                int j = jb + jp * 2;
                if (j < NS) {
                    unsigned dst = sbase + bufo + (unsigned)(c2 * 128 + jp * 2) * 8;
                    cp_async16(dst, ktf + (c2 * 720 + j) * 2);
                    cp_async16(dst + 1024 * 8, vtf + (c2 * 720 + j) * 2);
                }
            }
            asm volatile("cp.async.commit_group;");
        }

        const unsigned long long* ks = sbuf + (t & 1) * 2048;
        const unsigned long long* vs = ks + 1024;
        int jb = t * 128;
        #pragma unroll
        for (int sub = 0; sub < 4; sub++) {
            int jl = sub * 32 + lane;
            bool ok = (jb + jl) < NS;
            unsigned long long sco2[4] = {0ull, 0ull, 0ull, 0ull};
            #pragma unroll
            for (int c2 = 0; c2 < 8; c2++) {
                unsigned long long kv = ks[c2 * 128 + jl];
                sco2[0] = ffma2(qreg[0][c2], kv, sco2[0]);
                sco2[1] = ffma2(qreg[1][c2], kv, sco2[1]);
                sco2[2] = ffma2(qreg[2][c2], kv, sco2[2]);
                sco2[3] = ffma2(qreg[3][c2], kv, sco2[3]);
            }
            unsigned long long p2[4];
            #pragma unroll
            for (int tq = 0; tq < 4; tq++) {
                float lo, hi;
                unpack2(sco2[tq], lo, hi);
                float pe = ok ? ex2f(lo + hi) : 0.0f;
                l[tq] += pe;
                p2[tq] = pack2(pe, pe);
            }
            #pragma unroll
            for (int c2 = 0; c2 < 8; c2++) {
                unsigned long long vv = vs[c2 * 128 + jl];
                acc2[0][c2] = ffma2(p2[0], vv, acc2[0][c2]);
                acc2[1][c2] = ffma2(p2[1], vv, acc2[1][c2]);
                acc2[2][c2] = ffma2(p2[2], vv, acc2[2][c2]);
                acc2[3][c2] = ffma2(p2[3], vv, acc2[3][c2]);
            }
        }
    }

    #pragma unroll
    for (int tq = 0; tq < 4; tq++)
        #pragma unroll
        for (int off = 16; off; off >>= 1)
            l[tq] += __shfl_xor_sync(0xffffffffu, l[tq], off);
    float linv[4];
    #pragma unroll
    for (int tq = 0; tq < 4; tq++) linv[tq] = 1.0f / l[tq];

    __syncthreads();
    unsigned long long* red = sbuf + w * 528;
    #pragma unroll
    for (int ps = 0; ps < 2; ps++) {
        #pragma unroll
        for (int tq2 = 0; tq2 < 2; tq2++)
            #pragma unroll
            for (int c2 = 0; c2 < 8; c2++)
                red[(tq2 * 8 + c2) * 33 + lane] = acc2[ps * 2 + tq2][c2];
        __syncwarp();
        int tql = lane >> 4, cl = lane & 15;
        const float* base = (const float*)&red[(tql * 8 + (cl >> 1)) * 33];
        int hf = cl & 1;
        float v = 0.f;
        #pragma unroll
        for (int ll = 0; ll < 32; ll++) v += base[ll * 2 + hf];
        float li = linv[ps * 2 + tql];
        int i = i0 + w * 4 + ps * 2 + tql;
        if (i < NS)
            g_cat[(size_t)(s * NS + i) * 2 * DD + DD + h * 16 + cl] = v * li;
        __syncwarp();
    }
}

// ============================================================
// Kernel F: final projection, 16 rows/block, 4-way k-split, f32x2.
// ============================================================
__global__ __launch_bounds__(256) void final_kernel(const float* __restrict__ Wp,
                                                    float* __restrict__ out) {
    __shared__ float cs[16][2 * DD];
    __shared__ float pa[4][16][64];
    int s = blockIdx.x;
    int n0 = blockIdx.y * 16;
    int tid = threadIdx.x;

    #pragma unroll
    for (int half = 0; half < 2; half++) {
        int idx = half * 256 + tid;
        int r = idx >> 5, k4 = (idx & 31) * 4;
        int nn = min(n0 + r, NS - 1);
        *(float4*)&cs[r][k4] = *(const float4*)&g_cat[(size_t)(s * NS + nn) * 2 * DD + k4];
    }
    __syncthreads();

    int c = tid & 63, kg = tid >> 6;
    unsigned long long acc2[16];
    #pragma unroll
    for (int r = 0; r < 16; r++) acc2[r] = 0ull;
    for (int k0 = kg * 32; k0 < kg * 32 + 32; k0 += 2) {
        const float* w0 = (k0 < 64) ? (Wp + k0 * DD) : (g_Wc + (k0 - 64) * DD);
        unsigned long long wv = pack2(w0[c], w0[DD + c]);
        #pragma unroll
        for (int r = 0; r < 16; r++) {
            unsigned long long cv = *(const unsigned long long*)&cs[r][k0];
            acc2[r] = ffma2(cv, wv, acc2[r]);
        }
    }
    #pragma unroll
    for (int r = 0; r < 16; r++) {
        float lo, hi;
        unpack2(acc2[r], lo, hi);
        pa[kg][r][c] = lo + hi;
    }
    __syncthreads();

    if (kg == 0) {
        #pragma unroll
        for (int r = 0; r < 16; r++) {
            int n = n0 + r;
            if (n < NS)
                out[(size_t)(s * NS + n) * DD + c] =
                    pa[0][r][c] + pa[1][r][c] + pa[2][r][c] + pa[3][r][c] + g_bc[c];
        }
    }
}

// ============================================================
extern "C" void kernel_launch(void* const* d_in, const int* in_sizes, int n_in,
                              void* d_out, int out_size) {
    const float* x      = (const float*)d_in[0];
    const int*   adj    = (const int*)d_in[1];
    const int*   ind    = (const int*)d_in[2];
    const int*   outd   = (const int*)d_in[3];
    const float* in_emb = (const float*)d_in[4];
    const float* out_emb= (const float*)d_in[5];
    const float* W      = (const float*)d_in[6];
    const float* a1     = (const float*)d_in[7];
    const float* a2     = (const float*)d_in[8];
    const float* Wq     = (const float*)d_in[9];
    const float* bq     = (const float*)d_in[10];
    const float* Wk     = (const float*)d_in[11];
    const float* bk     = (const float*)d_in[12];
    const float* Wv     = (const float*)d_in[13];
    const float* bv     = (const float*)d_in[14];
    const float* Wo     = (const float*)d_in[15];
    const float* bo     = (const float*)d_in[16];
    const float* Wp     = (const float*)d_in[17];
    const float* bp     = (const float*)d_in[18];
    float* out = (float*)d_out;

    pre_kernel<<<229, 256>>>(adj, in_emb, out_emb, ind, outd, W, a1, a2, Wo, bo, Wp, bp);
    proj_kernel<<<dim3(NSAMP, (NS + BROWS - 1) / BROWS), 256>>>(x, W, Wq, bq, Wk, bk, Wv, bv);
    gat_kernel<<<dim3(NSAMP, NTILE), 256>>>();
    mha_kernel<<<dim3(NSAMP, NTILE, 4), 128>>>();
    final_kernel<<<dim3(NSAMP, NTILE), 256>>>(Wp, out);
}

// round 12
// speedup vs baseline: 1.0904x; 1.0055x over previous
#include <cuda_runtime.h>
#include <math.h>

#define NS 716
#define DD 64
#define NSAMP 48
#define NTILE 45            // ceil(716/16)
#define FINF 3.402823466e38f
#define LOG2E 1.4426950408889634f

// ---- scratch (device globals; no allocation) ----
__device__ float g_emb[NS * DD];
__device__ float g_Whp[NSAMP * 360 * 128];        // pair-interleaved: [s][j/2][c][j&1]
__device__ float g_Wh1[NSAMP * NS];               // pre-scaled by log2e
__device__ float g_Wh2[NSAMP * NS];               // pre-scaled by log2e
__device__ float g_q[NSAMP * NS * DD];
__device__ float g_kt2[NSAMP * 4 * 8 * 720 * 2];  // [s][h][c2][j][half]
__device__ float g_vt2[NSAMP * 4 * 8 * 720 * 2];
__device__ float g_cat[NSAMP * NS * 2 * DD];
__device__ unsigned g_cmask[NTILE * NS];
__device__ float g_wa1[DD];
__device__ float g_wa2[DD];
__device__ float g_Wc[DD * DD];   // Wo @ Wp[64:,:]
__device__ float g_bc[DD];        // bo @ Wp[64:,:] + bp

// ---- packed f32x2 helpers (sm_103a) ----
__device__ __forceinline__ unsigned long long pack2(float lo, float hi) {
    unsigned long long r;
    asm("mov.b64 %0, {%1, %2};" : "=l"(r) : "f"(lo), "f"(hi));
    return r;
}
__device__ __forceinline__ void unpack2(unsigned long long v, float& lo, float& hi) {
    asm("mov.b64 {%0, %1}, %2;" : "=f"(lo), "=f"(hi) : "l"(v));
}
__device__ __forceinline__ unsigned long long ffma2(unsigned long long a,
                                                    unsigned long long b,
                                                    unsigned long long c) {
    unsigned long long d;
    asm("fma.rn.f32x2 %0, %1, %2, %3;" : "=l"(d) : "l"(a), "l"(b), "l"(c));
    return d;
}
__device__ __forceinline__ unsigned long long add2(unsigned long long a,
                                                   unsigned long long b) {
    unsigned long long d;
    asm("add.rn.f32x2 %0, %1, %2;" : "=l"(d) : "l"(a), "l"(b));
    return d;
}
__device__ __forceinline__ float ex2f(float x) {
    float y;
    asm("ex2.approx.ftz.f32 %0, %1;" : "=f"(y) : "f"(x));
    return y;
}
__device__ __forceinline__ void cp_async16(unsigned sa, const void* g) {
    asm volatile("cp.async.cg.shared.global [%0], [%1], 16;" :: "r"(sa), "l"(g));
}

// ============================================================
// Kernel PRE: adjacency pack + embedding gather + weight prep + Whp pad
// grid 229 x 256
// ============================================================
__global__ void pre_kernel(const int* __restrict__ adj,
                           const float* __restrict__ in_emb,
                           const float* __restrict__ out_emb,
                           const int* __restrict__ ind,
                           const int* __restrict__ outd,
                           const float* __restrict__ W,
                           const float* __restrict__ a1, const float* __restrict__ a2,
                           const float* __restrict__ Wo, const float* __restrict__ bo,
                           const float* __restrict__ Wp, const float* __restrict__ bp) {
    int b = blockIdx.x, tid = threadIdx.x;
    if (b < 135) {
        int t = b / 3;
        int j = (b % 3) * 256 + tid;
        if (j < NS) {
            unsigned w = 0;
            #pragma unroll
            for (int ti = 0; ti < 16; ti++) {
                int i = t * 16 + ti;
                if (i < NS && adj[i * NS + j] != 0) w |= (1u << ti);
            }
            g_cmask[t * NS + j] = w;
        }
    } else if (b < 180) {
        int idx = (b - 135) * 256 + tid;
        if (idx < NS * 16) {
            int n = idx >> 4;
            int c4 = (idx & 15) * 4;
            float4 a = *(const float4*)&in_emb[ind[n] * DD + c4];
            float4 bb = *(const float4*)&out_emb[outd[n] * DD + c4];
            float4 r = {a.x + bb.x, a.y + bb.y, a.z + bb.z, a.w + bb.w};
            *(float4*)&g_emb[n * DD + c4] = r;
        }
    } else if (b == 180) {
        if (tid < DD) {
            float s1 = 0.f, s2 = 0.f;
            #pragma unroll 8
            for (int c = 0; c < DD; c++) {
                float w = W[tid * DD + c];
                s1 = fmaf(w, a1[c], s1);
                s2 = fmaf(w, a2[c], s2);
            }
            g_wa1[tid] = s1 * LOG2E; g_wa2[tid] = s2 * LOG2E;
            float bsum = bp[tid];
            #pragma unroll 8
            for (int m = 0; m < DD; m++) bsum = fmaf(bo[m], Wp[(DD + m) * DD + tid], bsum);
            g_bc[tid] = bsum;
        }
        for (int o = tid; o < DD * DD; o += 256) {
            int k = o >> 6, c = o & 63;
            float acc = 0.f;
            #pragma unroll 8
            for (int m = 0; m < DD; m++)
                acc = fmaf(Wo[k * DD + m], Wp[(DD + m) * DD + c], acc);
            g_Wc[o] = acc;
        }
    } else {
        int s = b - 181;          // 0..47
        int j = 716 + (tid >> 6); // 716..719
        int c = tid & 63;
        g_Whp[(size_t)s * 360 * 128 + (j >> 1) * 128 + c * 2 + (j & 1)] = 0.f;
    }
}

// ============================================================
// Kernel B: fused projections + Wh1/Wh2. f32x2 inner; smem-staged
// transposed stores (coalesced writeout). grid (48, 23), block 256.
// ============================================================
#define BROWS 32
__global__ __launch_bounds__(256) void proj_kernel(
    const float* __restrict__ x,
    const float* __restrict__ W,  const float* __restrict__ Wq, const float* __restrict__ bq,
    const float* __restrict__ Wk, const float* __restrict__ bk,
    const float* __restrict__ Wv, const float* __restrict__ bv) {
    __shared__ float xs[BROWS][DD];
    __shared__ float ys[BROWS][DD];
    __shared__ float stw[BROWS][DD];
    __shared__ float stk[BROWS][DD];
    __shared__ float stv[BROWS][DD];
    int s = blockIdx.x;
    int n0 = blockIdx.y * BROWS;
    int tid = threadIdx.x, lane = tid & 31, w = tid >> 5;

    #pragma unroll
    for (int half = 0; half < 2; half++) {
        int idx = half * 256 + tid;
        int r = idx >> 4, k4 = (idx & 15) * 4;
        int nn = min(n0 + r, NS - 1);
        float4 xv = *(const float4*)&x[(size_t)(s * NS + nn) * DD + k4];
        float4 ev = *(const float4*)&g_emb[nn * DD + k4];
        *(float4*)&xs[r][k4] = xv;
        float4 yv = {xv.x + ev.x, xv.y + ev.y, xv.z + ev.z, xv.w + ev.w};
        *(float4*)&ys[r][k4] = yv;
    }
    __syncthreads();

    // Wh1/Wh2 (log2e-scaled via g_wa1/g_wa2)
    {
        float wa10 = g_wa1[lane], wa11 = g_wa1[32 + lane];
        float wa20 = g_wa2[lane], wa21 = g_wa2[32 + lane];
        #pragma unroll
        for (int rr = 0; rr < 4; rr++) {
            int r = w * 4 + rr, n = n0 + r;
            float x0 = xs[r][lane], x1 = xs[r][32 + lane];
            float s1 = x0 * wa10 + x1 * wa11;
            float s2 = x0 * wa20 + x1 * wa21;
            #pragma unroll
            for (int off = 16; off; off >>= 1) {
                s1 += __shfl_xor_sync(0xffffffffu, s1, off);
                s2 += __shfl_xor_sync(0xffffffffu, s2, off);
            }
            if (lane == 0 && n < NS) {
                g_Wh1[s * NS + n] = s1;
                g_Wh2[s * NS + n] = s2;
            }
        }
    }

    int m = tid >> 6, c = tid & 63;
    const float* wp = (m == 0) ? W : (m == 1) ? Wq : (m == 2) ? Wk : Wv;
    float bias = 0.f;
    if (m == 1) bias = bq[c]; else if (m == 2) bias = bk[c]; else if (m == 3) bias = bv[c];

    unsigned long long wcol2[32];
    #pragma unroll
    for (int k2 = 0; k2 < 32; k2++)
        wcol2[k2] = pack2(wp[(2 * k2) * DD + c], wp[(2 * k2 + 1) * DD + c]);

    float* st = (m == 0) ? &stw[0][0] : (m == 2) ? &stk[0][0] : &stv[0][0];

    for (int r = 0; r < BROWS; r++) {
        int n = n0 + r;
        float acc = 0.f;
        if (n < NS) {
            const float* src = (m == 0) ? xs[r] : ys[r];
            unsigned long long acc2 = pack2(bias, 0.f);
            #pragma unroll
            for (int k2 = 0; k2 < 32; k2 += 2) {
                ulonglong2 sv = *(const ulonglong2*)&src[k2 * 2];
                acc2 = ffma2(sv.x, wcol2[k2], acc2);
                acc2 = ffma2(sv.y, wcol2[k2 + 1], acc2);
            }
            float lo, hi;
            unpack2(acc2, lo, hi);
            acc = lo + hi;
        }
        if (m == 1) {
            if (n < NS) g_q[(size_t)(s * NS + n) * DD + c] = acc;
        } else {
            st[r * DD + c] = acc;     // zero for n >= NS
        }
    }
    __syncthreads();

    // --- coalesced writeout: Whp (2048 floats) ---
    float* whbase = g_Whp + (size_t)s * 360 * 128 + (n0 >> 1) * 128;
    #pragma unroll
    for (int o4 = tid; o4 < 512; o4 += 256) {
        int o = o4 * 4;
        int prl = o >> 7;            // 0..15
        int cc = (o & 127) >> 1;     // even c
        if ((n0 >> 1) + prl < 360) {
            float4 vv;
            vv.x = stw[prl * 2 + 0][cc];
            vv.y = stw[prl * 2 + 1][cc];
            vv.z = stw[prl * 2 + 0][cc + 1];
            vv.w = stw[prl * 2 + 1][cc + 1];
            *(float4*)&whbase[prl * 128 + cc * 2] = vv;
        }
    }
    // --- kt2 / vt2 (2048 floats each) ---
    #pragma unroll
    for (int pass = 0; pass < 2; pass++) {
        const float* stx = pass ? &stv[0][0] : &stk[0][0];
        float* gdst = pass ? g_vt2 : g_kt2;
        #pragma unroll
        for (int o4 = tid; o4 < 512; o4 += 256) {
            int o = o4 * 4;
            int hc = o >> 6;         // h*8+c2
            int rl = (o & 63) >> 1;  // even local row
            int h = hc >> 3, c2 = hc & 7;
            int cbase = h * 16 + c2 * 2;
            if (n0 + rl < 720) {
                float4 vv;
                vv.x = stx[(rl + 0) * DD + cbase];
                vv.y = stx[(rl + 0) * DD + cbase + 1];
                vv.z = stx[(rl + 1) * DD + cbase];
                vv.w = stx[(rl + 1) * DD + cbase + 1];
                *(float4*)&gdst[(size_t)((s * 4 + h) * 8 + c2) * 1440 + (n0 + rl) * 2] = vv;
            }
        }
    }
}

// ============================================================
// Kernel D: GAT. grid (48,45), block 256. No-max exp2 softmax;
// dual-branch lrelu via add.f32x2; j-paired f32x2 PV.
// ============================================================
__global__ __launch_bounds__(256) void gat_kernel() {
    __shared__ float p[16][720];
    __shared__ float red[8][16];
    __shared__ float rowsum[16];

    int s = blockIdx.x, t = blockIdx.y;
    int i0 = t * 16;
    int tid = threadIdx.x, lane = tid & 31, w = tid >> 5;
    const unsigned* __restrict__ cm = g_cmask + t * NS;
    const float* __restrict__ wh2 = g_Wh2 + s * NS;

    unsigned long long whb[16];
    #pragma unroll
    for (int ti = 0; ti < 16; ti++) {
        int i = min(i0 + ti, NS - 1);
        float v = g_Wh1[s * NS + i];
        whb[ti] = pack2(v, 0.2f * v);
    }

    // main pass: exp2(lrelu) + sum, no max subtraction (args <= ~15, safe)
    float lsum[16];
    #pragma unroll
    for (int ti = 0; ti < 16; ti++) lsum[ti] = 0.f;
    for (int j = tid; j < 720; j += 256) {
        bool in = j < NS;
        float w2 = in ? wh2[j] : 0.f;
        unsigned mk = in ? cm[j] : 0u;
        unsigned long long w2p = pack2(w2, 0.2f * w2);
        #pragma unroll
        for (int ti = 0; ti < 16; ti++) {
            float lo, hi;
            unpack2(add2(whb[ti], w2p), lo, hi);
            float arg = fmaxf(lo, hi);
            float pe = ((mk >> ti) & 1u) ? ex2f(arg) : 0.0f;
            p[ti][j] = pe;
            lsum[ti] += pe;
        }
    }
    #pragma unroll
    for (int ti = 0; ti < 16; ti++)
        #pragma unroll
        for (int off = 16; off; off >>= 1)
            lsum[ti] += __shfl_xor_sync(0xffffffffu, lsum[ti], off);
    if (lane == 0) {
        #pragma unroll
        for (int ti = 0; ti < 16; ti++) red[w][ti] = lsum[ti];
    }
    __syncthreads();
    if (tid < 16) {
        float ss = red[0][tid];
        #pragma unroll
        for (int ww = 1; ww < 8; ww++) ss += red[ww][tid];
        rowsum[tid] = ss;
    }
    __syncthreads();

    // PV: j-paired f32x2
    int c = tid & 63, g = tid >> 6;
    unsigned long long acc2[16];
    #pragma unroll
    for (int ti = 0; ti < 16; ti++) acc2[ti] = 0ull;
    const unsigned long long* __restrict__ Whp2 =
        (const unsigned long long*)(g_Whp + (size_t)s * 360 * 128);
    for (int j0 = g * 8; j0 < 720; j0 += 32) {
        int pr = j0 >> 1;
        unsigned long long w0 = Whp2[(pr + 0) * 64 + c];
        unsigned long long w1 = Whp2[(pr + 1) * 64 + c];
        unsigned long long w2 = Whp2[(pr + 2) * 64 + c];
        unsigned long long w3 = Whp2[(pr + 3) * 64 + c];
        #pragma unroll
        for (int ti = 0; ti < 16; ti++) {
            ulonglong2 pa = *(const ulonglong2*)&p[ti][j0];
            ulonglong2 pb = *(const ulonglong2*)&p[ti][j0 + 4];
            acc2[ti] = ffma2(pa.x, w0, acc2[ti]);
            acc2[ti] = ffma2(pa.y, w1, acc2[ti]);
            acc2[ti] = ffma2(pb.x, w2, acc2[ti]);
            acc2[ti] = ffma2(pb.y, w3, acc2[ti]);
        }
    }
    float acc[16];
    #pragma unroll
    for (int ti = 0; ti < 16; ti++) {
        float lo, hi;
        unpack2(acc2[ti], lo, hi);
        acc[ti] = lo + hi;
    }
    __syncthreads();

    float* partial = &p[0][0];
    #pragma unroll
    for (int ti = 0; ti < 16; ti++) partial[(g * 16 + ti) * 64 + c] = acc[ti];
    __syncthreads();

    if (g == 0) {
        #pragma unroll
        for (int ti = 0; ti < 16; ti++) {
            int i = i0 + ti;
            if (i >= NS) continue;
            float v = (partial[ti * 64 + c] + partial[(16 + ti) * 64 + c] +
                       partial[(32 + ti) * 64 + c] + partial[(48 + ti) * 64 + c]) / rowsum[ti];
            v = v > 0.f ? v : expm1f(v);
            g_cat[(size_t)(s * NS + i) * 2 * DD + c] = v;
        }
    }
}

// ============================================================
// Kernel E: MHA — cp.async double-buffered, 4 q/warp, f32x2, exp2 domain.
// grid (48, 45, 4), block 128 (4 warps).
// ============================================================
__global__ __launch_bounds__(128, 3) void mha_kernel() {
    __shared__ __align__(16) unsigned long long sbuf[4096];

    int s = blockIdx.x;
    int i0 = blockIdx.y * 16;
    int h = blockIdx.z;
    int tid = threadIdx.x, lane = tid & 31, w = tid >> 5;

    unsigned long long qreg[4][8];
    #pragma unroll
    for (int tq = 0; tq < 4; tq++) {
        int iq = min(i0 + w * 4 + tq, NS - 1);
        const float2* qp2 = (const float2*)(g_q + (size_t)(s * NS + iq) * DD + h * 16);
        #pragma unroll
        for (int c2 = 0; c2 < 8; c2++) {
            float2 v = qp2[c2];
            qreg[tq][c2] = pack2(v.x * (0.25f * LOG2E), v.y * (0.25f * LOG2E));
        }
    }

    const float* __restrict__ ktf = g_kt2 + (size_t)(s * 4 + h) * 8 * 720 * 2;
    const float* __restrict__ vtf = g_vt2 + (size_t)(s * 4 + h) * 8 * 720 * 2;
    unsigned sbase = (unsigned)__cvta_generic_to_shared(sbuf);

    unsigned long long acc2[4][8];
    #pragma unroll
    for (int tq = 0; tq < 4; tq++)
        #pragma unroll
        for (int c2 = 0; c2 < 8; c2++) acc2[tq][c2] = 0ull;
    float l[4] = {0.f, 0.f, 0.f, 0.f};

    {
        #pragma unroll
        for (int i = 0; i < 4; i++) {
            int f = i * 128 + tid;
            int c2 = f >> 6, jp = f & 63;
            int j = jp * 2;
            if (j < NS) {
                unsigned dst = sbase + (unsigned)(c2 * 128 + jp * 2) * 8;
                cp_async16(dst, ktf + (c2 * 720 + j) * 2);
                cp_async16(dst + 1024 * 8, vtf + (c2 * 720 + j) * 2);
            }
        }
        asm volatile("cp.async.commit_group;");
    }

    for (int t = 0; t < 6; t++) {
        asm volatile("cp.async.wait_group 0;");
        __syncthreads();
        if (t < 5) {
            int jb = (t + 1) * 128;
            unsigned bufo = ((unsigned)((t + 1) & 1)) * 2048 * 8;
            #pragma unroll
            for (int i = 0; i < 4; i++) {
                int f = i * 128 + tid;
                int c2 = f >> 6, jp = f & 63;
                int j = jb + jp * 2;
                if (j < NS) {
                    unsigned dst = sbase + bufo + (unsigned)(c2 * 128 + jp * 2) * 8;
                    cp_async16(dst, ktf + (c2 * 720 + j) * 2);
                    cp_async16(dst + 1024 * 8, vtf + (c2 * 720 + j) * 2);
                }
            }
            asm volatile("cp.async.commit_group;");
        }

        const unsigned long long* ks = sbuf + (t & 1) * 2048;
        const unsigned long long* vs = ks + 1024;
        int jb = t * 128;
        #pragma unroll
        for (int sub = 0; sub < 4; sub++) {
            int jl = sub * 32 + lane;
            bool ok = (jb + jl) < NS;
            unsigned long long sco2[4] = {0ull, 0ull, 0ull, 0ull};
            #pragma unroll
            for (int c2 = 0; c2 < 8; c2++) {
                unsigned long long kv = ks[c2 * 128 + jl];
                sco2[0] = ffma2(qreg[0][c2], kv, sco2[0]);
                sco2[1] = ffma2(qreg[1][c2], kv, sco2[1]);
                sco2[2] = ffma2(qreg[2][c2], kv, sco2[2]);
                sco2[3] = ffma2(qreg[3][c2], kv, sco2[3]);
            }
            unsigned long long p2[4];
            #pragma unroll
            for (int tq = 0; tq < 4; tq++) {
                float lo, hi;
                unpack2(sco2[tq], lo, hi);
                float pe = ok ? ex2f(lo + hi) : 0.0f;
                l[tq] += pe;
                p2[tq] = pack2(pe, pe);
            }
            #pragma unroll
            for (int c2 = 0; c2 < 8; c2++) {
                unsigned long long vv = vs[c2 * 128 + jl];
                acc2[0][c2] = ffma2(p2[0], vv, acc2[0][c2]);
                acc2[1][c2] = ffma2(p2[1], vv, acc2[1][c2]);
                acc2[2][c2] = ffma2(p2[2], vv, acc2[2][c2]);
                acc2[3][c2] = ffma2(p2[3], vv, acc2[3][c2]);
            }
        }
    }

    #pragma unroll
    for (int tq = 0; tq < 4; tq++)
        #pragma unroll
        for (int off = 16; off; off >>= 1)
            l[tq] += __shfl_xor_sync(0xffffffffu, l[tq], off);
    float linv[4];
    #pragma unroll
    for (int tq = 0; tq < 4; tq++) linv[tq] = 1.0f / l[tq];

    __syncthreads();
    unsigned long long* red = sbuf + w * 528;
    #pragma unroll
    for (int ps = 0; ps < 2; ps++) {
        #pragma unroll
        for (int tq2 = 0; tq2 < 2; tq2++)
            #pragma unroll
            for (int c2 = 0; c2 < 8; c2++)
                red[(tq2 * 8 + c2) * 33 + lane] = acc2[ps * 2 + tq2][c2];
        __syncwarp();
        int tql = lane >> 4, cl = lane & 15;
        const float* base = (const float*)&red[(tql * 8 + (cl >> 1)) * 33];
        int hf = cl & 1;
        float v = 0.f;
        #pragma unroll
        for (int ll = 0; ll < 32; ll++) v += base[ll * 2 + hf];
        float li = linv[ps * 2 + tql];
        int i = i0 + w * 4 + ps * 2 + tql;
        if (i < NS)
            g_cat[(size_t)(s * NS + i) * 2 * DD + DD + h * 16 + cl] = v * li;
        __syncwarp();
    }
}

// ============================================================
// Kernel F: final projection, 16 rows/block, 4-way k-split, f32x2.
// ============================================================
__global__ __launch_bounds__(256) void final_kernel(const float* __restrict__ Wp,
                                                    float* __restrict__ out) {
    __shared__ float cs[16][2 * DD];
    __shared__ float pa[4][16][64];
    int s = blockIdx.x;
    int n0 = blockIdx.y * 16;
    int tid = threadIdx.x;

    #pragma unroll
    for (int half = 0; half < 2; half++) {
        int idx = half * 256 + tid;
        int r = idx >> 5, k4 = (idx & 31) * 4;
        int nn = min(n0 + r, NS - 1);
        *(float4*)&cs[r][k4] = *(const float4*)&g_cat[(size_t)(s * NS + nn) * 2 * DD + k4];
    }
    __syncthreads();

    int c = tid & 63, kg = tid >> 6;
    unsigned long long acc2[16];
    #pragma unroll
    for (int r = 0; r < 16; r++) acc2[r] = 0ull;
    for (int k0 = kg * 32; k0 < kg * 32 + 32; k0 += 2) {
        const float* w0 = (k0 < 64) ? (Wp + k0 * DD) : (g_Wc + (k0 - 64) * DD);
        unsigned long long wv = pack2(w0[c], w0[DD + c]);
        #pragma unroll
        for (int r = 0; r < 16; r++) {
            unsigned long long cv = *(const unsigned long long*)&cs[r][k0];
            acc2[r] = ffma2(cv, wv, acc2[r]);
        }
    }
    #pragma unroll
    for (int r = 0; r < 16; r++) {
        float lo, hi;
        unpack2(acc2[r], lo, hi);
        pa[kg][r][c] = lo + hi;
    }
    __syncthreads();

    if (kg == 0) {
        #pragma unroll
        for (int r = 0; r < 16; r++) {
            int n = n0 + r;
            if (n < NS)
                out[(size_t)(s * NS + n) * DD + c] =
                    pa[0][r][c] + pa[1][r][c] + pa[2][r][c] + pa[3][r][c] + g_bc[c];
        }
    }
}

// ============================================================
extern "C" void kernel_launch(void* const* d_in, const int* in_sizes, int n_in,
                              void* d_out, int out_size) {
    const float* x      = (const float*)d_in[0];
    const int*   adj    = (const int*)d_in[1];
    const int*   ind    = (const int*)d_in[2];
    const int*   outd   = (const int*)d_in[3];
    const float* in_emb = (const float*)d_in[4];
    const float* out_emb= (const float*)d_in[5];
    const float* W      = (const float*)d_in[6];
    const float* a1     = (const float*)d_in[7];
    const float* a2     = (const float*)d_in[8];
    const float* Wq     = (const float*)d_in[9];
    const float* bq     = (const float*)d_in[10];
    const float* Wk     = (const float*)d_in[11];
    const float* bk     = (const float*)d_in[12];
    const float* Wv     = (const float*)d_in[13];
    const float* bv     = (const float*)d_in[14];
    const float* Wo     = (const float*)d_in[15];
    const float* bo     = (const float*)d_in[16];
    const float* Wp     = (const float*)d_in[17];
    const float* bp     = (const float*)d_in[18];
    float* out = (float*)d_out;

    pre_kernel<<<229, 256>>>(adj, in_emb, out_emb, ind, outd, W, a1, a2, Wo, bo, Wp, bp);
    proj_kernel<<<dim3(NSAMP, (NS + BROWS - 1) / BROWS), 256>>>(x, W, Wq, bq, Wk, bk, Wv, bv);
    gat_kernel<<<dim3(NSAMP, NTILE), 256>>>();
    mha_kernel<<<dim3(NSAMP, NTILE, 4), 128>>>();
    final_kernel<<<dim3(NSAMP, NTILE), 256>>>(Wp, out);
}

// round 13
// speedup vs baseline: 1.3557x; 1.2434x over previous
#include <cuda_runtime.h>
#include <cuda_fp16.h>
#include <mma.h>
#include <math.h>

using namespace nvcuda;

#define NS 716
#define DD 64
#define NSAMP 48
#define NTILE 45            // ceil(716/16)
#define FINF 3.402823466e38f
#define LOG2E 1.4426950408889634f

// ---- scratch (device globals; no allocation) ----
__device__ float g_emb[NS * DD];
__device__ float g_Whp[NSAMP * 360 * 128];        // pair-interleaved: [s][j/2][c][j&1]
__device__ float g_Wh1[NSAMP * NS];               // pre-scaled by log2e
__device__ float g_Wh2[NSAMP * NS];               // pre-scaled by log2e
__device__ float g_q[NSAMP * NS * DD];
__device__ __half g_kh[NSAMP * 4 * 720 * 16];     // fp16 [s][h][j][c]
__device__ __half g_vh[NSAMP * 4 * 720 * 16];
__device__ float g_cat[NSAMP * NS * 2 * DD];
__device__ unsigned g_cmask[NTILE * NS];
__device__ float g_wa1[DD];
__device__ float g_wa2[DD];
__device__ float g_Wc[DD * DD];   // Wo @ Wp[64:,:]
__device__ float g_bc[DD];        // bo @ Wp[64:,:] + bp

// ---- packed f32x2 helpers (sm_103a) ----
__device__ __forceinline__ unsigned long long pack2(float lo, float hi) {
    unsigned long long r;
    asm("mov.b64 %0, {%1, %2};" : "=l"(r) : "f"(lo), "f"(hi));
    return r;
}
__device__ __forceinline__ void unpack2(unsigned long long v, float& lo, float& hi) {
    asm("mov.b64 {%0, %1}, %2;" : "=f"(lo), "=f"(hi) : "l"(v));
}
__device__ __forceinline__ unsigned long long ffma2(unsigned long long a,
                                                    unsigned long long b,
                                                    unsigned long long c) {
    unsigned long long d;
    asm("fma.rn.f32x2 %0, %1, %2, %3;" : "=l"(d) : "l"(a), "l"(b), "l"(c));
    return d;
}
__device__ __forceinline__ unsigned long long add2(unsigned long long a,
                                                   unsigned long long b) {
    unsigned long long d;
    asm("add.rn.f32x2 %0, %1, %2;" : "=l"(d) : "l"(a), "l"(b));
    return d;
}
__device__ __forceinline__ float ex2f(float x) {
    float y;
    asm("ex2.approx.ftz.f32 %0, %1;" : "=f"(y) : "f"(x));
    return y;
}
__device__ __forceinline__ void cp_async16(unsigned sa, const void* g) {
    asm volatile("cp.async.cg.shared.global [%0], [%1], 16;" :: "r"(sa), "l"(g));
}

// ============================================================
// Kernel PRE: adjacency pack + embedding gather + weight prep + Whp pad
// grid 229 x 256
// ============================================================
__global__ void pre_kernel(const int* __restrict__ adj,
                           const float* __restrict__ in_emb,
                           const float* __restrict__ out_emb,
                           const int* __restrict__ ind,
                           const int* __restrict__ outd,
                           const float* __restrict__ W,
                           const float* __restrict__ a1, const float* __restrict__ a2,
                           const float* __restrict__ Wo, const float* __restrict__ bo,
                           const float* __restrict__ Wp, const float* __restrict__ bp) {
    int b = blockIdx.x, tid = threadIdx.x;
    if (b < 135) {
        int t = b / 3;
        int j = (b % 3) * 256 + tid;
        if (j < NS) {
            unsigned w = 0;
            #pragma unroll
            for (int ti = 0; ti < 16; ti++) {
                int i = t * 16 + ti;
                if (i < NS && adj[i * NS + j] != 0) w |= (1u << ti);
            }
            g_cmask[t * NS + j] = w;
        }
    } else if (b < 180) {
        int idx = (b - 135) * 256 + tid;
        if (idx < NS * 16) {
            int n = idx >> 4;
            int c4 = (idx & 15) * 4;
            float4 a = *(const float4*)&in_emb[ind[n] * DD + c4];
            float4 bb = *(const float4*)&out_emb[outd[n] * DD + c4];
            float4 r = {a.x + bb.x, a.y + bb.y, a.z + bb.z, a.w + bb.w};
            *(float4*)&g_emb[n * DD + c4] = r;
        }
    } else if (b == 180) {
        if (tid < DD) {
            float s1 = 0.f, s2 = 0.f;
            #pragma unroll 8
            for (int c = 0; c < DD; c++) {
                float w = W[tid * DD + c];
                s1 = fmaf(w, a1[c], s1);
                s2 = fmaf(w, a2[c], s2);
            }
            g_wa1[tid] = s1 * LOG2E; g_wa2[tid] = s2 * LOG2E;
            float bsum = bp[tid];
            #pragma unroll 8
            for (int m = 0; m < DD; m++) bsum = fmaf(bo[m], Wp[(DD + m) * DD + tid], bsum);
            g_bc[tid] = bsum;
        }
        for (int o = tid; o < DD * DD; o += 256) {
            int k = o >> 6, c = o & 63;
            float acc = 0.f;
            #pragma unroll 8
            for (int m = 0; m < DD; m++)
                acc = fmaf(Wo[k * DD + m], Wp[(DD + m) * DD + c], acc);
            g_Wc[o] = acc;
        }
    } else {
        int s = b - 181;          // 0..47
        int j = 716 + (tid >> 6); // 716..719
        int c = tid & 63;
        g_Whp[(size_t)s * 360 * 128 + (j >> 1) * 128 + c * 2 + (j & 1)] = 0.f;
    }
}

// ============================================================
// Kernel B: fused projections + Wh1/Wh2. f32x2 inner; smem-staged
// coalesced writeout (Whp fp32, k/v fp16). grid (48, 23), block 256.
// ============================================================
#define BROWS 32
__global__ __launch_bounds__(256) void proj_kernel(
    const float* __restrict__ x,
    const float* __restrict__ W,  const float* __restrict__ Wq, const float* __restrict__ bq,
    const float* __restrict__ Wk, const float* __restrict__ bk,
    const float* __restrict__ Wv, const float* __restrict__ bv) {
    __shared__ float xs[BROWS][DD];
    __shared__ float ys[BROWS][DD];
    __shared__ float stw[BROWS][DD];
    __shared__ float stk[BROWS][DD];
    __shared__ float stv[BROWS][DD];
    int s = blockIdx.x;
    int n0 = blockIdx.y * BROWS;
    int tid = threadIdx.x, lane = tid & 31, w = tid >> 5;

    #pragma unroll
    for (int half = 0; half < 2; half++) {
        int idx = half * 256 + tid;
        int r = idx >> 4, k4 = (idx & 15) * 4;
        int nn = min(n0 + r, NS - 1);
        float4 xv = *(const float4*)&x[(size_t)(s * NS + nn) * DD + k4];
        float4 ev = *(const float4*)&g_emb[nn * DD + k4];
        *(float4*)&xs[r][k4] = xv;
        float4 yv = {xv.x + ev.x, xv.y + ev.y, xv.z + ev.z, xv.w + ev.w};
        *(float4*)&ys[r][k4] = yv;
    }
    __syncthreads();

    // Wh1/Wh2 (log2e-scaled via g_wa1/g_wa2)
    {
        float wa10 = g_wa1[lane], wa11 = g_wa1[32 + lane];
        float wa20 = g_wa2[lane], wa21 = g_wa2[32 + lane];
        #pragma unroll
        for (int rr = 0; rr < 4; rr++) {
            int r = w * 4 + rr, n = n0 + r;
            float x0 = xs[r][lane], x1 = xs[r][32 + lane];
            float s1 = x0 * wa10 + x1 * wa11;
            float s2 = x0 * wa20 + x1 * wa21;
            #pragma unroll
            for (int off = 16; off; off >>= 1) {
                s1 += __shfl_xor_sync(0xffffffffu, s1, off);
                s2 += __shfl_xor_sync(0xffffffffu, s2, off);
            }
            if (lane == 0 && n < NS) {
                g_Wh1[s * NS + n] = s1;
                g_Wh2[s * NS + n] = s2;
            }
        }
    }

    int m = tid >> 6, c = tid & 63;
    const float* wp = (m == 0) ? W : (m == 1) ? Wq : (m == 2) ? Wk : Wv;
    float bias = 0.f;
    if (m == 1) bias = bq[c]; else if (m == 2) bias = bk[c]; else if (m == 3) bias = bv[c];

    unsigned long long wcol2[32];
    #pragma unroll
    for (int k2 = 0; k2 < 32; k2++)
        wcol2[k2] = pack2(wp[(2 * k2) * DD + c], wp[(2 * k2 + 1) * DD + c]);

    float* st = (m == 0) ? &stw[0][0] : (m == 2) ? &stk[0][0] : &stv[0][0];

    for (int r = 0; r < BROWS; r++) {
        int n = n0 + r;
        float acc = 0.f;
        if (n < NS) {
            const float* src = (m == 0) ? xs[r] : ys[r];
            unsigned long long acc2 = pack2(bias, 0.f);
            #pragma unroll
            for (int k2 = 0; k2 < 32; k2 += 2) {
                ulonglong2 sv = *(const ulonglong2*)&src[k2 * 2];
                acc2 = ffma2(sv.x, wcol2[k2], acc2);
                acc2 = ffma2(sv.y, wcol2[k2 + 1], acc2);
            }
            float lo, hi;
            unpack2(acc2, lo, hi);
            acc = lo + hi;
        }
        if (m == 1) {
            if (n < NS) g_q[(size_t)(s * NS + n) * DD + c] = acc;
        } else {
            st[r * DD + c] = acc;     // zero for n >= NS
        }
    }
    __syncthreads();

    // --- coalesced writeout: Whp (2048 floats) ---
    float* whbase = g_Whp + (size_t)s * 360 * 128 + (n0 >> 1) * 128;
    #pragma unroll
    for (int o4 = tid; o4 < 512; o4 += 256) {
        int o = o4 * 4;
        int prl = o >> 7;            // 0..15
        int cc = (o & 127) >> 1;     // even c
        if ((n0 >> 1) + prl < 360) {
            float4 vv;
            vv.x = stw[prl * 2 + 0][cc];
            vv.y = stw[prl * 2 + 1][cc];
            vv.z = stw[prl * 2 + 0][cc + 1];
            vv.w = stw[prl * 2 + 1][cc + 1];
            *(float4*)&whbase[prl * 128 + cc * 2] = vv;
        }
    }
    // --- k/v fp16 writeout: [s][h][j][c], rows padded with zeros to 720 ---
    #pragma unroll
    for (int pass = 0; pass < 2; pass++) {
        const float* stx = pass ? &stv[0][0] : &stk[0][0];
        __half* gdst = pass ? g_vh : g_kh;
        #pragma unroll
        for (int o2 = tid; o2 < 1024; o2 += 256) {
            int cp = o2 & 7;          // c-pair 0..7
            int nl = (o2 >> 3) & 31;  // local row
            int hh = o2 >> 8;         // head 0..3
            int n = n0 + nl;
            if (n < 720) {
                float a = stx[nl * DD + hh * 16 + cp * 2];
                float b = stx[nl * DD + hh * 16 + cp * 2 + 1];
                *(__half2*)&gdst[(size_t)((s * 4 + hh) * 720 + n) * 16 + cp * 2] =
                    __floats2half2_rn(a, b);
            }
        }
    }
}

// ============================================================
// Kernel D: GAT. grid (48,45), block 256. No-max exp2 softmax;
// dual-branch lrelu via add.f32x2; j-paired f32x2 PV. (unchanged)
// ============================================================
__global__ __launch_bounds__(256) void gat_kernel() {
    __shared__ float p[16][720];
    __shared__ float red[8][16];
    __shared__ float rowsum[16];

    int s = blockIdx.x, t = blockIdx.y;
    int i0 = t * 16;
    int tid = threadIdx.x, lane = tid & 31, w = tid >> 5;
    const unsigned* __restrict__ cm = g_cmask + t * NS;
    const float* __restrict__ wh2 = g_Wh2 + s * NS;

    unsigned long long whb[16];
    #pragma unroll
    for (int ti = 0; ti < 16; ti++) {
        int i = min(i0 + ti, NS - 1);
        float v = g_Wh1[s * NS + i];
        whb[ti] = pack2(v, 0.2f * v);
    }

    float lsum[16];
    #pragma unroll
    for (int ti = 0; ti < 16; ti++) lsum[ti] = 0.f;
    for (int j = tid; j < 720; j += 256) {
        bool in = j < NS;
        float w2 = in ? wh2[j] : 0.f;
        unsigned mk = in ? cm[j] : 0u;
        unsigned long long w2p = pack2(w2, 0.2f * w2);
        #pragma unroll
        for (int ti = 0; ti < 16; ti++) {
            float lo, hi;
            unpack2(add2(whb[ti], w2p), lo, hi);
            float arg = fmaxf(lo, hi);
            float pe = ((mk >> ti) & 1u) ? ex2f(arg) : 0.0f;
            p[ti][j] = pe;
            lsum[ti] += pe;
        }
    }
    #pragma unroll
    for (int ti = 0; ti < 16; ti++)
        #pragma unroll
        for (int off = 16; off; off >>= 1)
            lsum[ti] += __shfl_xor_sync(0xffffffffu, lsum[ti], off);
    if (lane == 0) {
        #pragma unroll
        for (int ti = 0; ti < 16; ti++) red[w][ti] = lsum[ti];
    }
    __syncthreads();
    if (tid < 16) {
        float ss = red[0][tid];
        #pragma unroll
        for (int ww = 1; ww < 8; ww++) ss += red[ww][tid];
        rowsum[tid] = ss;
    }
    __syncthreads();

    int c = tid & 63, g = tid >> 6;
    unsigned long long acc2[16];
    #pragma unroll
    for (int ti = 0; ti < 16; ti++) acc2[ti] = 0ull;
    const unsigned long long* __restrict__ Whp2 =
        (const unsigned long long*)(g_Whp + (size_t)s * 360 * 128);
    for (int j0 = g * 8; j0 < 720; j0 += 32) {
        int pr = j0 >> 1;
        unsigned long long w0 = Whp2[(pr + 0) * 64 + c];
        unsigned long long w1 = Whp2[(pr + 1) * 64 + c];
        unsigned long long w2 = Whp2[(pr + 2) * 64 + c];
        unsigned long long w3 = Whp2[(pr + 3) * 64 + c];
        #pragma unroll
        for (int ti = 0; ti < 16; ti++) {
            ulonglong2 pa = *(const ulonglong2*)&p[ti][j0];
            ulonglong2 pb = *(const ulonglong2*)&p[ti][j0 + 4];
            acc2[ti] = ffma2(pa.x, w0, acc2[ti]);
            acc2[ti] = ffma2(pa.y, w1, acc2[ti]);
            acc2[ti] = ffma2(pb.x, w2, acc2[ti]);
            acc2[ti] = ffma2(pb.y, w3, acc2[ti]);
        }
    }
    float acc[16];
    #pragma unroll
    for (int ti = 0; ti < 16; ti++) {
        float lo, hi;
        unpack2(acc2[ti], lo, hi);
        acc[ti] = lo + hi;
    }
    __syncthreads();

    float* partial = &p[0][0];
    #pragma unroll
    for (int ti = 0; ti < 16; ti++) partial[(g * 16 + ti) * 64 + c] = acc[ti];
    __syncthreads();

    if (g == 0) {
        #pragma unroll
        for (int ti = 0; ti < 16; ti++) {
            int i = i0 + ti;
            if (i >= NS) continue;
            float v = (partial[ti * 64 + c] + partial[(16 + ti) * 64 + c] +
                       partial[(32 + ti) * 64 + c] + partial[(48 + ti) * 64 + c]) / rowsum[ti];
            v = v > 0.f ? v : expm1f(v);
            g_cat[(size_t)(s * NS + i) * 2 * DD + c] = v;
        }
    }
}

// ============================================================
// Kernel E: MHA via fp16 tensor cores (wmma m16n16k16).
// grid (48, 45, 4), block 128 (4 warps). Per warp: own 16-j chunk stream,
// per-warp cp.async ring, QK mma -> exp in smem -> PV mma + l-via-ones mma.
// ============================================================
__global__ __launch_bounds__(128) void mha_kernel() {
    __shared__ __align__(32) __half qh[256];
    __shared__ __align__(32) float scoresm[4][256];
    __shared__ __align__(32) __half ph[4][256];
    __shared__ __align__(32) __half ring[4][4][2][256];   // [warp][stage][k/v][16x16]
    __shared__ __align__(32) float osm[4][256];
    __shared__ __align__(32) float lsm[4][256];

    int s = blockIdx.x, i0 = blockIdx.y * 16, h = blockIdx.z;
    int tid = threadIdx.x, lane = tid & 31, w = tid >> 5;

    // stage q tile as fp16, pre-scaled into exp2 domain
    for (int idx = tid; idx < 256; idx += 128) {
        int r = idx >> 4, c = idx & 15;
        int iq = min(i0 + r, NS - 1);
        float v = g_q[(size_t)(s * NS + iq) * DD + h * 16 + c] * (0.25f * LOG2E);
        qh[idx] = __float2half(v);
    }
    __syncthreads();

    wmma::fragment<wmma::matrix_a, 16, 16, 16, __half, wmma::row_major> qa;
    wmma::load_matrix_sync(qa, qh, 16);
    wmma::fragment<wmma::matrix_b, 16, 16, 16, __half, wmma::row_major> bones;
    wmma::fill_fragment(bones, __float2half(1.0f));
    wmma::fragment<wmma::accumulator, 16, 16, 16, float> ofrag, lfrag;
    wmma::fill_fragment(ofrag, 0.0f);
    wmma::fill_fragment(lfrag, 0.0f);

    const __half* kg = g_kh + (size_t)(s * 4 + h) * 720 * 16;
    const __half* vg = g_vh + (size_t)(s * 4 + h) * 720 * 16;

    // prologue: fill 3 stages (chunks w, w+4, w+8 all < 45)
    #pragma unroll
    for (int st = 0; st < 3; st++) {
        int ch = w + st * 4;
        unsigned dk = (unsigned)__cvta_generic_to_shared(&ring[w][st][0][0]) + lane * 16;
        unsigned dv = (unsigned)__cvta_generic_to_shared(&ring[w][st][1][0]) + lane * 16;
        cp_async16(dk, (const char*)(kg + ch * 256) + lane * 16);
        cp_async16(dv, (const char*)(vg + ch * 256) + lane * 16);
        asm volatile("cp.async.commit_group;");
    }

    int nch = (48 - w) / 4;   // 12,11,11,11 chunks for warps 0..3
    for (int i = 0; i < nch; i++) {
        int ch = w + i * 4;
        asm volatile("cp.async.wait_group 2;");
        int st = i & 3;

        // QK: scores(16q x 16j) = q(16x16) x k^T
        wmma::fragment<wmma::matrix_b, 16, 16, 16, __half, wmma::col_major> kb;
        wmma::load_matrix_sync(kb, &ring[w][st][0][0], 16);
        wmma::fragment<wmma::accumulator, 16, 16, 16, float> cfrag;
        wmma::fill_fragment(cfrag, 0.0f);
        wmma::mma_sync(cfrag, qa, kb, cfrag);
        wmma::store_matrix_sync(&scoresm[w][0], cfrag, 16, wmma::mem_row_major);
        __syncwarp();

        // exp2 + j-mask in smem coords, write fp16 p
        int jb = ch * 16;
        #pragma unroll
        for (int e = 0; e < 8; e++) {
            int idx = e * 32 + lane;
            int c = idx & 15;
            float sc = scoresm[w][idx];
            ph[w][idx] = (jb + c < NS) ? __float2half(ex2f(sc)) : __float2half(0.0f);
        }
        __syncwarp();

        // PV + l accumulation (p x ones)
        wmma::fragment<wmma::matrix_a, 16, 16, 16, __half, wmma::row_major> pa;
        wmma::load_matrix_sync(pa, &ph[w][0], 16);
        wmma::fragment<wmma::matrix_b, 16, 16, 16, __half, wmma::row_major> vb;
        wmma::load_matrix_sync(vb, &ring[w][st][1][0], 16);
        wmma::mma_sync(ofrag, pa, vb, ofrag);
        wmma::mma_sync(lfrag, pa, bones, lfrag);

        // refill stage (i+3)%4 with chunk w+(i+3)*4
        int chn = w + (i + 3) * 4;
        if (chn < 45) {
            int stn = (i + 3) & 3;
            unsigned dk = (unsigned)__cvta_generic_to_shared(&ring[w][stn][0][0]) + lane * 16;
            unsigned dv = (unsigned)__cvta_generic_to_shared(&ring[w][stn][1][0]) + lane * 16;
            cp_async16(dk, (const char*)(kg + chn * 256) + lane * 16);
            cp_async16(dv, (const char*)(vg + chn * 256) + lane * 16);
        }
        asm volatile("cp.async.commit_group;");
    }
    asm volatile("cp.async.wait_group 0;");

    wmma::store_matrix_sync(&osm[w][0], ofrag, 16, wmma::mem_row_major);
    wmma::store_matrix_sync(&lsm[w][0], lfrag, 16, wmma::mem_row_major);
    __syncthreads();

    for (int idx = tid; idx < 256; idx += 128) {
        int r = idx >> 4, c = idx & 15;
        float o = osm[0][idx] + osm[1][idx] + osm[2][idx] + osm[3][idx];
        float l = lsm[0][r * 16] + lsm[1][r * 16] + lsm[2][r * 16] + lsm[3][r * 16];
        int i = i0 + r;
        if (i < NS)
            g_cat[(size_t)(s * NS + i) * 2 * DD + DD + h * 16 + c] = o / l;
    }
}

// ============================================================
// Kernel F: final projection, 16 rows/block, 4-way k-split, f32x2.
// ============================================================
__global__ __launch_bounds__(256) void final_kernel(const float* __restrict__ Wp,
                                                    float* __restrict__ out) {
    __shared__ float cs[16][2 * DD];
    __shared__ float pa[4][16][64];
    int s = blockIdx.x;
    int n0 = blockIdx.y * 16;
    int tid = threadIdx.x;

    #pragma unroll
    for (int half = 0; half < 2; half++) {
        int idx = half * 256 + tid;
        int r = idx >> 5, k4 = (idx & 31) * 4;
        int nn = min(n0 + r, NS - 1);
        *(float4*)&cs[r][k4] = *(const float4*)&g_cat[(size_t)(s * NS + nn) * 2 * DD + k4];
    }
    __syncthreads();

    int c = tid & 63, kg = tid >> 6;
    unsigned long long acc2[16];
    #pragma unroll
    for (int r = 0; r < 16; r++) acc2[r] = 0ull;
    for (int k0 = kg * 32; k0 < kg * 32 + 32; k0 += 2) {
        const float* w0 = (k0 < 64) ? (Wp + k0 * DD) : (g_Wc + (k0 - 64) * DD);
        unsigned long long wv = pack2(w0[c], w0[DD + c]);
        #pragma unroll
        for (int r = 0; r < 16; r++) {
            unsigned long long cv = *(const unsigned long long*)&cs[r][k0];
            acc2[r] = ffma2(cv, wv, acc2[r]);
        }
    }
    #pragma unroll
    for (int r = 0; r < 16; r++) {
        float lo, hi;
        unpack2(acc2[r], lo, hi);
        pa[kg][r][c] = lo + hi;
    }
    __syncthreads();

    if (kg == 0) {
        #pragma unroll
        for (int r = 0; r < 16; r++) {
            int n = n0 + r;
            if (n < NS)
                out[(size_t)(s * NS + n) * DD + c] =
                    pa[0][r][c] + pa[1][r][c] + pa[2][r][c] + pa[3][r][c] + g_bc[c];
        }
    }
}

// ============================================================
extern "C" void kernel_launch(void* const* d_in, const int* in_sizes, int n_in,
                              void* d_out, int out_size) {
    const float* x      = (const float*)d_in[0];
    const int*   adj    = (const int*)d_in[1];
    const int*   ind    = (const int*)d_in[2];
    const int*   outd   = (const int*)d_in[3];
    const float* in_emb = (const float*)d_in[4];
    const float* out_emb= (const float*)d_in[5];
    const float* W      = (const float*)d_in[6];
    const float* a1     = (const float*)d_in[7];
    const float* a2     = (const float*)d_in[8];
    const float* Wq     = (const float*)d_in[9];
    const float* bq     = (const float*)d_in[10];
    const float* Wk     = (const float*)d_in[11];
    const float* bk     = (const float*)d_in[12];
    const float* Wv     = (const float*)d_in[13];
    const float* bv     = (const float*)d_in[14];
    const float* Wo     = (const float*)d_in[15];
    const float* bo     = (const float*)d_in[16];
    const float* Wp     = (const float*)d_in[17];
    const float* bp     = (const float*)d_in[18];
    float* out = (float*)d_out;

    pre_kernel<<<229, 256>>>(adj, in_emb, out_emb, ind, outd, W, a1, a2, Wo, bo, Wp, bp);
    proj_kernel<<<dim3(NSAMP, (NS + BROWS - 1) / BROWS), 256>>>(x, W, Wq, bq, Wk, bk, Wv, bv);
    gat_kernel<<<dim3(NSAMP, NTILE), 256>>>();
    mha_kernel<<<dim3(NSAMP, NTILE, 4), 128>>>();
    final_kernel<<<dim3(NSAMP, NTILE), 256>>>(Wp, out);
}

// round 14
// speedup vs baseline: 1.3643x; 1.0063x over previous
#include <cuda_runtime.h>
#include <cuda_fp16.h>
#include <mma.h>
#include <math.h>

using namespace nvcuda;

#define NS 716
#define DD 64
#define NSAMP 48
#define NTILE 45            // ceil(716/16)
#define FINF 3.402823466e38f
#define LOG2E 1.4426950408889634f

// ---- scratch (device globals; no allocation) ----
__device__ float g_emb[NS * DD];
__device__ float g_Whp[NSAMP * 360 * 128];        // pair-interleaved: [s][j/2][c][j&1]
__device__ float g_Wh1[NSAMP * NS];               // pre-scaled by log2e
__device__ float g_Wh2[NSAMP * NS];               // pre-scaled by log2e
__device__ float g_q[NSAMP * NS * DD];
__device__ __half g_kh[NSAMP * 4 * 720 * 16];     // fp16 [s][h][j][c], rows 716..719 zero
__device__ __half g_vh[NSAMP * 4 * 720 * 16];
__device__ float g_cat[NSAMP * NS * 2 * DD];
__device__ unsigned g_cmask[NTILE * NS];
__device__ float g_wa1[DD];
__device__ float g_wa2[DD];
__device__ float g_Wc[DD * DD];   // Wo @ Wp[64:,:]
__device__ float g_bc[DD];        // bo @ Wp[64:,:] + bp

// ---- packed f32x2 helpers (sm_103a) ----
__device__ __forceinline__ unsigned long long pack2(float lo, float hi) {
    unsigned long long r;
    asm("mov.b64 %0, {%1, %2};" : "=l"(r) : "f"(lo), "f"(hi));
    return r;
}
__device__ __forceinline__ void unpack2(unsigned long long v, float& lo, float& hi) {
    asm("mov.b64 {%0, %1}, %2;" : "=f"(lo), "=f"(hi) : "l"(v));
}
__device__ __forceinline__ unsigned long long ffma2(unsigned long long a,
                                                    unsigned long long b,
                                                    unsigned long long c) {
    unsigned long long d;
    asm("fma.rn.f32x2 %0, %1, %2, %3;" : "=l"(d) : "l"(a), "l"(b), "l"(c));
    return d;
}
__device__ __forceinline__ unsigned long long add2(unsigned long long a,
                                                   unsigned long long b) {
    unsigned long long d;
    asm("add.rn.f32x2 %0, %1, %2;" : "=l"(d) : "l"(a), "l"(b));
    return d;
}
__device__ __forceinline__ float ex2f(float x) {
    float y;
    asm("ex2.approx.ftz.f32 %0, %1;" : "=f"(y) : "f"(x));
    return y;
}
__device__ __forceinline__ void cp_async16(unsigned sa, const void* g) {
    asm volatile("cp.async.cg.shared.global [%0], [%1], 16;" :: "r"(sa), "l"(g));
}

// ============================================================
// Kernel PRE: adjacency pack + embedding gather + weight prep + Whp pad
// grid 229 x 256
// ============================================================
__global__ void pre_kernel(const int* __restrict__ adj,
                           const float* __restrict__ in_emb,
                           const float* __restrict__ out_emb,
                           const int* __restrict__ ind,
                           const int* __restrict__ outd,
                           const float* __restrict__ W,
                           const float* __restrict__ a1, const float* __restrict__ a2,
                           const float* __restrict__ Wo, const float* __restrict__ bo,
                           const float* __restrict__ Wp, const float* __restrict__ bp) {
    int b = blockIdx.x, tid = threadIdx.x;
    if (b < 135) {
        int t = b / 3;
        int j = (b % 3) * 256 + tid;
        if (j < NS) {
            unsigned w = 0;
            #pragma unroll
            for (int ti = 0; ti < 16; ti++) {
                int i = t * 16 + ti;
                if (i < NS && adj[i * NS + j] != 0) w |= (1u << ti);
            }
            g_cmask[t * NS + j] = w;
        }
    } else if (b < 180) {
        int idx = (b - 135) * 256 + tid;
        if (idx < NS * 16) {
            int n = idx >> 4;
            int c4 = (idx & 15) * 4;
            float4 a = *(const float4*)&in_emb[ind[n] * DD + c4];
            float4 bb = *(const float4*)&out_emb[outd[n] * DD + c4];
            float4 r = {a.x + bb.x, a.y + bb.y, a.z + bb.z, a.w + bb.w};
            *(float4*)&g_emb[n * DD + c4] = r;
        }
    } else if (b == 180) {
        if (tid < DD) {
            float s1 = 0.f, s2 = 0.f;
            #pragma unroll 8
            for (int c = 0; c < DD; c++) {
                float w = W[tid * DD + c];
                s1 = fmaf(w, a1[c], s1);
                s2 = fmaf(w, a2[c], s2);
            }
            g_wa1[tid] = s1 * LOG2E; g_wa2[tid] = s2 * LOG2E;
            float bsum = bp[tid];
            #pragma unroll 8
            for (int m = 0; m < DD; m++) bsum = fmaf(bo[m], Wp[(DD + m) * DD + tid], bsum);
            g_bc[tid] = bsum;
        }
        for (int o = tid; o < DD * DD; o += 256) {
            int k = o >> 6, c = o & 63;
            float acc = 0.f;
            #pragma unroll 8
            for (int m = 0; m < DD; m++)
                acc = fmaf(Wo[k * DD + m], Wp[(DD + m) * DD + c], acc);
            g_Wc[o] = acc;
        }
    } else {
        int s = b - 181;          // 0..47
        int j = 716 + (tid >> 6); // 716..719
        int c = tid & 63;
        g_Whp[(size_t)s * 360 * 128 + (j >> 1) * 128 + c * 2 + (j & 1)] = 0.f;
    }
}

// ============================================================
// Kernel B: fused projections + Wh1/Wh2. f32x2 inner; smem-staged
// coalesced writeout (Whp fp32, k/v fp16). grid (48, 23), block 256.
// ============================================================
#define BROWS 32
__global__ __launch_bounds__(256) void proj_kernel(
    const float* __restrict__ x,
    const float* __restrict__ W,  const float* __restrict__ Wq, const float* __restrict__ bq,
    const float* __restrict__ Wk, const float* __restrict__ bk,
    const float* __restrict__ Wv, const float* __restrict__ bv) {
    __shared__ float xs[BROWS][DD];
    __shared__ float ys[BROWS][DD];
    __shared__ float stw[BROWS][DD];
    __shared__ float stk[BROWS][DD];
    __shared__ float stv[BROWS][DD];
    int s = blockIdx.x;
    int n0 = blockIdx.y * BROWS;
    int tid = threadIdx.x, lane = tid & 31, w = tid >> 5;

    #pragma unroll
    for (int half = 0; half < 2; half++) {
        int idx = half * 256 + tid;
        int r = idx >> 4, k4 = (idx & 15) * 4;
        int nn = min(n0 + r, NS - 1);
        float4 xv = *(const float4*)&x[(size_t)(s * NS + nn) * DD + k4];
        float4 ev = *(const float4*)&g_emb[nn * DD + k4];
        *(float4*)&xs[r][k4] = xv;
        float4 yv = {xv.x + ev.x, xv.y + ev.y, xv.z + ev.z, xv.w + ev.w};
        *(float4*)&ys[r][k4] = yv;
    }
    __syncthreads();

    // Wh1/Wh2 (log2e-scaled via g_wa1/g_wa2)
    {
        float wa10 = g_wa1[lane], wa11 = g_wa1[32 + lane];
        float wa20 = g_wa2[lane], wa21 = g_wa2[32 + lane];
        #pragma unroll
        for (int rr = 0; rr < 4; rr++) {
            int r = w * 4 + rr, n = n0 + r;
            float x0 = xs[r][lane], x1 = xs[r][32 + lane];
            float s1 = x0 * wa10 + x1 * wa11;
            float s2 = x0 * wa20 + x1 * wa21;
            #pragma unroll
            for (int off = 16; off; off >>= 1) {
                s1 += __shfl_xor_sync(0xffffffffu, s1, off);
                s2 += __shfl_xor_sync(0xffffffffu, s2, off);
            }
            if (lane == 0 && n < NS) {
                g_Wh1[s * NS + n] = s1;
                g_Wh2[s * NS + n] = s2;
            }
        }
    }

    int m = tid >> 6, c = tid & 63;
    const float* wp = (m == 0) ? W : (m == 1) ? Wq : (m == 2) ? Wk : Wv;
    float bias = 0.f;
    if (m == 1) bias = bq[c]; else if (m == 2) bias = bk[c]; else if (m == 3) bias = bv[c];

    unsigned long long wcol2[32];
    #pragma unroll
    for (int k2 = 0; k2 < 32; k2++)
        wcol2[k2] = pack2(wp[(2 * k2) * DD + c], wp[(2 * k2 + 1) * DD + c]);

    float* st = (m == 0) ? &stw[0][0] : (m == 2) ? &stk[0][0] : &stv[0][0];

    for (int r = 0; r < BROWS; r++) {
        int n = n0 + r;
        float acc = 0.f;
        if (n < NS) {
            const float* src = (m == 0) ? xs[r] : ys[r];
            unsigned long long acc2 = pack2(bias, 0.f);
            #pragma unroll
            for (int k2 = 0; k2 < 32; k2 += 2) {
                ulonglong2 sv = *(const ulonglong2*)&src[k2 * 2];
                acc2 = ffma2(sv.x, wcol2[k2], acc2);
                acc2 = ffma2(sv.y, wcol2[k2 + 1], acc2);
            }
            float lo, hi;
            unpack2(acc2, lo, hi);
            acc = lo + hi;
        }
        if (m == 1) {
            if (n < NS) g_q[(size_t)(s * NS + n) * DD + c] = acc;
        } else {
            st[r * DD + c] = acc;     // zero for n >= NS
        }
    }
    __syncthreads();

    // --- coalesced writeout: Whp (2048 floats) ---
    float* whbase = g_Whp + (size_t)s * 360 * 128 + (n0 >> 1) * 128;
    #pragma unroll
    for (int o4 = tid; o4 < 512; o4 += 256) {
        int o = o4 * 4;
        int prl = o >> 7;            // 0..15
        int cc = (o & 127) >> 1;     // even c
        if ((n0 >> 1) + prl < 360) {
            float4 vv;
            vv.x = stw[prl * 2 + 0][cc];
            vv.y = stw[prl * 2 + 1][cc];
            vv.z = stw[prl * 2 + 0][cc + 1];
            vv.w = stw[prl * 2 + 1][cc + 1];
            *(float4*)&whbase[prl * 128 + cc * 2] = vv;
        }
    }
    // --- k/v fp16 writeout: [s][h][j][c], rows padded with zeros to 720 ---
    #pragma unroll
    for (int pass = 0; pass < 2; pass++) {
        const float* stx = pass ? &stv[0][0] : &stk[0][0];
        __half* gdst = pass ? g_vh : g_kh;
        #pragma unroll
        for (int o2 = tid; o2 < 1024; o2 += 256) {
            int cp = o2 & 7;          // c-pair 0..7
            int nl = (o2 >> 3) & 31;  // local row
            int hh = o2 >> 8;         // head 0..3
            int n = n0 + nl;
            if (n < 720) {
                float a = stx[nl * DD + hh * 16 + cp * 2];
                float b = stx[nl * DD + hh * 16 + cp * 2 + 1];
                *(__half2*)&gdst[(size_t)((s * 4 + hh) * 720 + n) * 16 + cp * 2] =
                    __floats2half2_rn(a, b);
            }
        }
    }
}

// ============================================================
// Kernel D: GAT. grid (48,45), block 256. No-max exp2 softmax;
// dual-branch lrelu via add.f32x2; j-paired f32x2 PV. (unchanged)
// ============================================================
__global__ __launch_bounds__(256) void gat_kernel() {
    __shared__ float p[16][720];
    __shared__ float red[8][16];
    __shared__ float rowsum[16];

    int s = blockIdx.x, t = blockIdx.y;
    int i0 = t * 16;
    int tid = threadIdx.x, lane = tid & 31, w = tid >> 5;
    const unsigned* __restrict__ cm = g_cmask + t * NS;
    const float* __restrict__ wh2 = g_Wh2 + s * NS;

    unsigned long long whb[16];
    #pragma unroll
    for (int ti = 0; ti < 16; ti++) {
        int i = min(i0 + ti, NS - 1);
        float v = g_Wh1[s * NS + i];
        whb[ti] = pack2(v, 0.2f * v);
    }

    float lsum[16];
    #pragma unroll
    for (int ti = 0; ti < 16; ti++) lsum[ti] = 0.f;
    for (int j = tid; j < 720; j += 256) {
        bool in = j < NS;
        float w2 = in ? wh2[j] : 0.f;
        unsigned mk = in ? cm[j] : 0u;
        unsigned long long w2p = pack2(w2, 0.2f * w2);
        #pragma unroll
        for (int ti = 0; ti < 16; ti++) {
            float lo, hi;
            unpack2(add2(whb[ti], w2p), lo, hi);
            float arg = fmaxf(lo, hi);
            float pe = ((mk >> ti) & 1u) ? ex2f(arg) : 0.0f;
            p[ti][j] = pe;
            lsum[ti] += pe;
        }
    }
    #pragma unroll
    for (int ti = 0; ti < 16; ti++)
        #pragma unroll
        for (int off = 16; off; off >>= 1)
            lsum[ti] += __shfl_xor_sync(0xffffffffu, lsum[ti], off);
    if (lane == 0) {
        #pragma unroll
        for (int ti = 0; ti < 16; ti++) red[w][ti] = lsum[ti];
    }
    __syncthreads();
    if (tid < 16) {
        float ss = red[0][tid];
        #pragma unroll
        for (int ww = 1; ww < 8; ww++) ss += red[ww][tid];
        rowsum[tid] = ss;
    }
    __syncthreads();

    int c = tid & 63, g = tid >> 6;
    unsigned long long acc2[16];
    #pragma unroll
    for (int ti = 0; ti < 16; ti++) acc2[ti] = 0ull;
    const unsigned long long* __restrict__ Whp2 =
        (const unsigned long long*)(g_Whp + (size_t)s * 360 * 128);
    for (int j0 = g * 8; j0 < 720; j0 += 32) {
        int pr = j0 >> 1;
        unsigned long long w0 = Whp2[(pr + 0) * 64 + c];
        unsigned long long w1 = Whp2[(pr + 1) * 64 + c];
        unsigned long long w2 = Whp2[(pr + 2) * 64 + c];
        unsigned long long w3 = Whp2[(pr + 3) * 64 + c];
        #pragma unroll
        for (int ti = 0; ti < 16; ti++) {
            ulonglong2 pa = *(const ulonglong2*)&p[ti][j0];
            ulonglong2 pb = *(const ulonglong2*)&p[ti][j0 + 4];
            acc2[ti] = ffma2(pa.x, w0, acc2[ti]);
            acc2[ti] = ffma2(pa.y, w1, acc2[ti]);
            acc2[ti] = ffma2(pb.x, w2, acc2[ti]);
            acc2[ti] = ffma2(pb.y, w3, acc2[ti]);
        }
    }
    float acc[16];
    #pragma unroll
    for (int ti = 0; ti < 16; ti++) {
        float lo, hi;
        unpack2(acc2[ti], lo, hi);
        acc[ti] = lo + hi;
    }
    __syncthreads();

    float* partial = &p[0][0];
    #pragma unroll
    for (int ti = 0; ti < 16; ti++) partial[(g * 16 + ti) * 64 + c] = acc[ti];
    __syncthreads();

    if (g == 0) {
        #pragma unroll
        for (int ti = 0; ti < 16; ti++) {
            int i = i0 + ti;
            if (i >= NS) continue;
            float v = (partial[ti * 64 + c] + partial[(16 + ti) * 64 + c] +
                       partial[(32 + ti) * 64 + c] + partial[(48 + ti) * 64 + c]) / rowsum[ti];
            v = v > 0.f ? v : expm1f(v);
            g_cat[(size_t)(s * NS + i) * 2 * DD + c] = v;
        }
    }
}

// ============================================================
// Kernel E: MHA via fp16 tensor cores (wmma m16n16k16).
// grid (48, 45, 4), block 128 (4 warps). Register exp on accumulator,
// exact l -= 4 padding compensation (k/v rows 716..719 are zero), and
// o/l epilogue overlaid onto the dead cp.async ring.
// ============================================================
__global__ __launch_bounds__(128) void mha_kernel() {
    __shared__ __align__(32) __half qh[256];
    __shared__ __align__(32) float scoresm[4][256];
    __shared__ __align__(32) __half ph[4][256];
    __shared__ __align__(16) __half ring[4][4][2][256];   // [warp][stage][k/v][16x16]

    int s = blockIdx.x, i0 = blockIdx.y * 16, h = blockIdx.z;
    int tid = threadIdx.x, lane = tid & 31, w = tid >> 5;

    // stage q tile as fp16, pre-scaled into exp2 domain
    for (int idx = tid; idx < 256; idx += 128) {
        int r = idx >> 4, c = idx & 15;
        int iq = min(i0 + r, NS - 1);
        float v = g_q[(size_t)(s * NS + iq) * DD + h * 16 + c] * (0.25f * LOG2E);
        qh[idx] = __float2half(v);
    }
    __syncthreads();

    wmma::fragment<wmma::matrix_a, 16, 16, 16, __half, wmma::row_major> qa;
    wmma::load_matrix_sync(qa, qh, 16);
    wmma::fragment<wmma::matrix_b, 16, 16, 16, __half, wmma::row_major> bones;
    wmma::fill_fragment(bones, __float2half(1.0f));
    wmma::fragment<wmma::accumulator, 16, 16, 16, float> ofrag, lfrag;
    wmma::fill_fragment(ofrag, 0.0f);
    wmma::fill_fragment(lfrag, 0.0f);

    const __half* kg = g_kh + (size_t)(s * 4 + h) * 720 * 16;
    const __half* vg = g_vh + (size_t)(s * 4 + h) * 720 * 16;

    // prologue: fill 3 stages (chunks w, w+4, w+8 all < 45)
    #pragma unroll
    for (int st = 0; st < 3; st++) {
        int ch = w + st * 4;
        unsigned dk = (unsigned)__cvta_generic_to_shared(&ring[w][st][0][0]) + lane * 16;
        unsigned dv = (unsigned)__cvta_generic_to_shared(&ring[w][st][1][0]) + lane * 16;
        cp_async16(dk, (const char*)(kg + ch * 256) + lane * 16);
        cp_async16(dv, (const char*)(vg + ch * 256) + lane * 16);
        asm volatile("cp.async.commit_group;");
    }

    int nch = (48 - w) / 4;   // 12,11,11,11 chunks for warps 0..3
    for (int i = 0; i < nch; i++) {
        asm volatile("cp.async.wait_group 2;");
        int st = i & 3;

        // QK: scores(16q x 16j) = q(16x16) x k^T
        wmma::fragment<wmma::matrix_b, 16, 16, 16, __half, wmma::col_major> kb;
        wmma::load_matrix_sync(kb, &ring[w][st][0][0], 16);
        wmma::fragment<wmma::accumulator, 16, 16, 16, float> cfrag;
        wmma::fill_fragment(cfrag, 0.0f);
        wmma::mma_sync(cfrag, qa, kb, cfrag);
        // exp2 in registers — no masking (padded columns compensated via l-4)
        #pragma unroll
        for (int e = 0; e < cfrag.num_elements; e++)
            cfrag.x[e] = ex2f(cfrag.x[e]);
        wmma::store_matrix_sync(&scoresm[w][0], cfrag, 16, wmma::mem_row_major);
        __syncwarp();

        // vectorized float->half: 1 lane = 8 values
        {
            int idx = lane * 8;
            float4 f0 = *(const float4*)&scoresm[w][idx];
            float4 f1 = *(const float4*)&scoresm[w][idx + 4];
            __half2 h0 = __floats2half2_rn(f0.x, f0.y);
            __half2 h1 = __floats2half2_rn(f0.z, f0.w);
            __half2 h2 = __floats2half2_rn(f1.x, f1.y);
            __half2 h3 = __floats2half2_rn(f1.z, f1.w);
            uint4 u;
            u.x = *(unsigned*)&h0; u.y = *(unsigned*)&h1;
            u.z = *(unsigned*)&h2; u.w = *(unsigned*)&h3;
            *(uint4*)&ph[w][idx] = u;
        }
        __syncwarp();

        // PV + l accumulation (p x ones)
        wmma::fragment<wmma::matrix_a, 16, 16, 16, __half, wmma::row_major> pa;
        wmma::load_matrix_sync(pa, &ph[w][0], 16);
        wmma::fragment<wmma::matrix_b, 16, 16, 16, __half, wmma::row_major> vb;
        wmma::load_matrix_sync(vb, &ring[w][st][1][0], 16);
        wmma::mma_sync(ofrag, pa, vb, ofrag);
        wmma::mma_sync(lfrag, pa, bones, lfrag);

        // refill stage (i+3)%4 with chunk w+(i+3)*4
        int chn = w + (i + 3) * 4;
        if (chn < 45) {
            int stn = (i + 3) & 3;
            unsigned dk = (unsigned)__cvta_generic_to_shared(&ring[w][stn][0][0]) + lane * 16;
            unsigned dv = (unsigned)__cvta_generic_to_shared(&ring[w][stn][1][0]) + lane * 16;
            cp_async16(dk, (const char*)(kg + chn * 256) + lane * 16);
            cp_async16(dv, (const char*)(vg + chn * 256) + lane * 16);
        }
        asm volatile("cp.async.commit_group;");
    }
    asm volatile("cp.async.wait_group 0;");

    // epilogue overlaid on the (now dead) ring: per warp 1024 floats available
    float* osmw = (float*)&ring[w][0][0][0];        // 256 floats
    float* lsmw = osmw + 256;                       // 256 floats
    wmma::store_matrix_sync(osmw, ofrag, 16, wmma::mem_row_major);
    wmma::store_matrix_sync(lsmw, lfrag, 16, wmma::mem_row_major);
    __syncthreads();

    const float* fb = (const float*)&ring[0][0][0][0];   // warp stride = 1024 floats
    for (int idx = tid; idx < 256; idx += 128) {
        int r = idx >> 4, c = idx & 15;
        float o = fb[idx] + fb[1024 + idx] + fb[2048 + idx] + fb[3072 + idx];
        float l = fb[256 + r * 16] + fb[1280 + r * 16] +
                  fb[2304 + r * 16] + fb[3328 + r * 16] - 4.0f;  // exact pad compensation
        int i = i0 + r;
        if (i < NS)
            g_cat[(size_t)(s * NS + i) * 2 * DD + DD + h * 16 + c] = o / l;
    }
}

// ============================================================
// Kernel F: final projection, 16 rows/block, 4-way k-split, f32x2.
// ============================================================
__global__ __launch_bounds__(256) void final_kernel(const float* __restrict__ Wp,
                                                    float* __restrict__ out) {
    __shared__ float cs[16][2 * DD];
    __shared__ float pa[4][16][64];
    int s = blockIdx.x;
    int n0 = blockIdx.y * 16;
    int tid = threadIdx.x;

    #pragma unroll
    for (int half = 0; half < 2; half++) {
        int idx = half * 256 + tid;
        int r = idx >> 5, k4 = (idx & 31) * 4;
        int nn = min(n0 + r, NS - 1);
        *(float4*)&cs[r][k4] = *(const float4*)&g_cat[(size_t)(s * NS + nn) * 2 * DD + k4];
    }
    __syncthreads();

    int c = tid & 63, kg = tid >> 6;
    unsigned long long acc2[16];
    #pragma unroll
    for (int r = 0; r < 16; r++) acc2[r] = 0ull;
    for (int k0 = kg * 32; k0 < kg * 32 + 32; k0 += 2) {
        const float* w0 = (k0 < 64) ? (Wp + k0 * DD) : (g_Wc + (k0 - 64) * DD);
        unsigned long long wv = pack2(w0[c], w0[DD + c]);
        #pragma unroll
        for (int r = 0; r < 16; r++) {
            unsigned long long cv = *(const unsigned long long*)&cs[r][k0];
            acc2[r] = ffma2(cv, wv, acc2[r]);
        }
    }
    #pragma unroll
    for (int r = 0; r < 16; r++) {
        float lo, hi;
        unpack2(acc2[r], lo, hi);
        pa[kg][r][c] = lo + hi;
    }
    __syncthreads();

    if (kg == 0) {
        #pragma unroll
        for (int r = 0; r < 16; r++) {
            int n = n0 + r;
            if (n < NS)
                out[(size_t)(s * NS + n) * DD + c] =
                    pa[0][r][c] + pa[1][r][c] + pa[2][r][c] + pa[3][r][c] + g_bc[c];
        }
    }
}

// ============================================================
extern "C" void kernel_launch(void* const* d_in, const int* in_sizes, int n_in,
                              void* d_out, int out_size) {
    const float* x      = (const float*)d_in[0];
    const int*   adj    = (const int*)d_in[1];
    const int*   ind    = (const int*)d_in[2];
    const int*   outd   = (const int*)d_in[3];
    const float* in_emb = (const float*)d_in[4];
    const float* out_emb= (const float*)d_in[5];
    const float* W      = (const float*)d_in[6];
    const float* a1     = (const float*)d_in[7];
    const float* a2     = (const float*)d_in[8];
    const float* Wq     = (const float*)d_in[9];
    const float* bq     = (const float*)d_in[10];
    const float* Wk     = (const float*)d_in[11];
    const float* bk     = (const float*)d_in[12];
    const float* Wv     = (const float*)d_in[13];
    const float* bv     = (const float*)d_in[14];
    const float* Wo     = (const float*)d_in[15];
    const float* bo     = (const float*)d_in[16];
    const float* Wp     = (const float*)d_in[17];
    const float* bp     = (const float*)d_in[18];
    float* out = (float*)d_out;

    pre_kernel<<<229, 256>>>(adj, in_emb, out_emb, ind, outd, W, a1, a2, Wo, bo, Wp, bp);
    proj_kernel<<<dim3(NSAMP, (NS + BROWS - 1) / BROWS), 256>>>(x, W, Wq, bq, Wk, bk, Wv, bv);
    gat_kernel<<<dim3(NSAMP, NTILE), 256>>>();
    mha_kernel<<<dim3(NSAMP, NTILE, 4), 128>>>();
    final_kernel<<<dim3(NSAMP, NTILE), 256>>>(Wp, out);
}

// round 15
// speedup vs baseline: 1.5321x; 1.1230x over previous
#include <cuda_runtime.h>
#include <cuda_fp16.h>
#include <mma.h>
#include <math.h>

using namespace nvcuda;

#define NS 716
#define DD 64
#define NSAMP 48
#define NTILE 45            // ceil(716/16)
#define FINF 3.402823466e38f
#define LOG2E 1.4426950408889634f

// ---- scratch (device globals; no allocation) ----
__device__ float g_emb[NS * DD];
__device__ float g_Whp[NSAMP * 360 * 128];        // pair-interleaved: [s][j/2][c][j&1]
__device__ float g_Wh1[NSAMP * NS];               // pre-scaled by log2e
__device__ float g_Wh2[NSAMP * NS];               // pre-scaled by log2e
__device__ float g_q[NSAMP * NS * DD];
__device__ __half g_kh[NSAMP * 4 * 720 * 16];     // fp16 [s][h][j][c], rows 716..719 zero
__device__ __half g_vh[NSAMP * 4 * 720 * 16];
__device__ float g_cat[NSAMP * NS * 2 * DD];
__device__ unsigned g_cmask[NTILE * NS];
__device__ float g_wa1[DD];
__device__ float g_wa2[DD];
__device__ float g_Wc[DD * DD];   // Wo @ Wp[64:,:]
__device__ float g_bc[DD];        // bo @ Wp[64:,:] + bp

// ---- packed f32x2 helpers (sm_103a) ----
__device__ __forceinline__ unsigned long long pack2(float lo, float hi) {
    unsigned long long r;
    asm("mov.b64 %0, {%1, %2};" : "=l"(r) : "f"(lo), "f"(hi));
    return r;
}
__device__ __forceinline__ void unpack2(unsigned long long v, float& lo, float& hi) {
    asm("mov.b64 {%0, %1}, %2;" : "=f"(lo), "=f"(hi) : "l"(v));
}
__device__ __forceinline__ unsigned long long ffma2(unsigned long long a,
                                                    unsigned long long b,
                                                    unsigned long long c) {
    unsigned long long d;
    asm("fma.rn.f32x2 %0, %1, %2, %3;" : "=l"(d) : "l"(a), "l"(b), "l"(c));
    return d;
}
__device__ __forceinline__ unsigned long long add2(unsigned long long a,
                                                   unsigned long long b) {
    unsigned long long d;
    asm("add.rn.f32x2 %0, %1, %2;" : "=l"(d) : "l"(a), "l"(b));
    return d;
}
__device__ __forceinline__ float ex2f(float x) {
    float y;
    asm("ex2.approx.ftz.f32 %0, %1;" : "=f"(y) : "f"(x));
    return y;
}
__device__ __forceinline__ void cp_async16(unsigned sa, const void* g) {
    asm volatile("cp.async.cg.shared.global [%0], [%1], 16;" :: "r"(sa), "l"(g));
}

// ============================================================
// Kernel PRE: adjacency pack + embedding gather + weight prep + Whp pad
// grid 229 x 256
// ============================================================
__global__ void pre_kernel(const int* __restrict__ adj,
                           const float* __restrict__ in_emb,
                           const float* __restrict__ out_emb,
                           const int* __restrict__ ind,
                           const int* __restrict__ outd,
                           const float* __restrict__ W,
                           const float* __restrict__ a1, const float* __restrict__ a2,
                           const float* __restrict__ Wo, const float* __restrict__ bo,
                           const float* __restrict__ Wp, const float* __restrict__ bp) {
    int b = blockIdx.x, tid = threadIdx.x;
    if (b < 135) {
        int t = b / 3;
        int j = (b % 3) * 256 + tid;
        if (j < NS) {
            unsigned w = 0;
            #pragma unroll
            for (int ti = 0; ti < 16; ti++) {
                int i = t * 16 + ti;
                if (i < NS && adj[i * NS + j] != 0) w |= (1u << ti);
            }
            g_cmask[t * NS + j] = w;
        }
    } else if (b < 180) {
        int idx = (b - 135) * 256 + tid;
        if (idx < NS * 16) {
            int n = idx >> 4;
            int c4 = (idx & 15) * 4;
            float4 a = *(const float4*)&in_emb[ind[n] * DD + c4];
            float4 bb = *(const float4*)&out_emb[outd[n] * DD + c4];
            float4 r = {a.x + bb.x, a.y + bb.y, a.z + bb.z, a.w + bb.w};
            *(float4*)&g_emb[n * DD + c4] = r;
        }
    } else if (b == 180) {
        if (tid < DD) {
            float s1 = 0.f, s2 = 0.f;
            #pragma unroll 8
            for (int c = 0; c < DD; c++) {
                float w = W[tid * DD + c];
                s1 = fmaf(w, a1[c], s1);
                s2 = fmaf(w, a2[c], s2);
            }
            g_wa1[tid] = s1 * LOG2E; g_wa2[tid] = s2 * LOG2E;
            float bsum = bp[tid];
            #pragma unroll 8
            for (int m = 0; m < DD; m++) bsum = fmaf(bo[m], Wp[(DD + m) * DD + tid], bsum);
            g_bc[tid] = bsum;
        }
        for (int o = tid; o < DD * DD; o += 256) {
            int k = o >> 6, c = o & 63;
            float acc = 0.f;
            #pragma unroll 8
            for (int m = 0; m < DD; m++)
                acc = fmaf(Wo[k * DD + m], Wp[(DD + m) * DD + c], acc);
            g_Wc[o] = acc;
        }
    } else {
        int s = b - 181;          // 0..47
        int j = 716 + (tid >> 6); // 716..719
        int c = tid & 63;
        g_Whp[(size_t)s * 360 * 128 + (j >> 1) * 128 + c * 2 + (j & 1)] = 0.f;
    }
}

// ============================================================
// Kernel B: fused projections + Wh1/Wh2. f32x2 inner; smem-staged
// coalesced writeout (Whp fp32, k/v fp16). grid (48, 23), block 256.
// ============================================================
#define BROWS 32
__global__ __launch_bounds__(256) void proj_kernel(
    const float* __restrict__ x,
    const float* __restrict__ W,  const float* __restrict__ Wq, const float* __restrict__ bq,
    const float* __restrict__ Wk, const float* __restrict__ bk,
    const float* __restrict__ Wv, const float* __restrict__ bv) {
    __shared__ float xs[BROWS][DD];
    __shared__ float ys[BROWS][DD];
    __shared__ float stw[BROWS][DD];
    __shared__ float stk[BROWS][DD];
    __shared__ float stv[BROWS][DD];
    int s = blockIdx.x;
    int n0 = blockIdx.y * BROWS;
    int tid = threadIdx.x, lane = tid & 31, w = tid >> 5;

    #pragma unroll
    for (int half = 0; half < 2; half++) {
        int idx = half * 256 + tid;
        int r = idx >> 4, k4 = (idx & 15) * 4;
        int nn = min(n0 + r, NS - 1);
        float4 xv = *(const float4*)&x[(size_t)(s * NS + nn) * DD + k4];
        float4 ev = *(const float4*)&g_emb[nn * DD + k4];
        *(float4*)&xs[r][k4] = xv;
        float4 yv = {xv.x + ev.x, xv.y + ev.y, xv.z + ev.z, xv.w + ev.w};
        *(float4*)&ys[r][k4] = yv;
    }
    __syncthreads();

    // Wh1/Wh2 (log2e-scaled via g_wa1/g_wa2)
    {
        float wa10 = g_wa1[lane], wa11 = g_wa1[32 + lane];
        float wa20 = g_wa2[lane], wa21 = g_wa2[32 + lane];
        #pragma unroll
        for (int rr = 0; rr < 4; rr++) {
            int r = w * 4 + rr, n = n0 + r;
            float x0 = xs[r][lane], x1 = xs[r][32 + lane];
            float s1 = x0 * wa10 + x1 * wa11;
            float s2 = x0 * wa20 + x1 * wa21;
            #pragma unroll
            for (int off = 16; off; off >>= 1) {
                s1 += __shfl_xor_sync(0xffffffffu, s1, off);
                s2 += __shfl_xor_sync(0xffffffffu, s2, off);
            }
            if (lane == 0 && n < NS) {
                g_Wh1[s * NS + n] = s1;
                g_Wh2[s * NS + n] = s2;
            }
        }
    }

    int m = tid >> 6, c = tid & 63;
    const float* wp = (m == 0) ? W : (m == 1) ? Wq : (m == 2) ? Wk : Wv;
    float bias = 0.f;
    if (m == 1) bias = bq[c]; else if (m == 2) bias = bk[c]; else if (m == 3) bias = bv[c];

    unsigned long long wcol2[32];
    #pragma unroll
    for (int k2 = 0; k2 < 32; k2++)
        wcol2[k2] = pack2(wp[(2 * k2) * DD + c], wp[(2 * k2 + 1) * DD + c]);

    float* st = (m == 0) ? &stw[0][0] : (m == 2) ? &stk[0][0] : &stv[0][0];

    for (int r = 0; r < BROWS; r++) {
        int n = n0 + r;
        float acc = 0.f;
        if (n < NS) {
            const float* src = (m == 0) ? xs[r] : ys[r];
            unsigned long long acc2 = pack2(bias, 0.f);
            #pragma unroll
            for (int k2 = 0; k2 < 32; k2 += 2) {
                ulonglong2 sv = *(const ulonglong2*)&src[k2 * 2];
                acc2 = ffma2(sv.x, wcol2[k2], acc2);
                acc2 = ffma2(sv.y, wcol2[k2 + 1], acc2);
            }
            float lo, hi;
            unpack2(acc2, lo, hi);
            acc = lo + hi;
        }
        if (m == 1) {
            if (n < NS) g_q[(size_t)(s * NS + n) * DD + c] = acc;
        } else {
            st[r * DD + c] = acc;     // zero for n >= NS
        }
    }
    __syncthreads();

    // --- coalesced writeout: Whp (2048 floats) ---
    float* whbase = g_Whp + (size_t)s * 360 * 128 + (n0 >> 1) * 128;
    #pragma unroll
    for (int o4 = tid; o4 < 512; o4 += 256) {
        int o = o4 * 4;
        int prl = o >> 7;            // 0..15
        int cc = (o & 127) >> 1;     // even c
        if ((n0 >> 1) + prl < 360) {
            float4 vv;
            vv.x = stw[prl * 2 + 0][cc];
            vv.y = stw[prl * 2 + 1][cc];
            vv.z = stw[prl * 2 + 0][cc + 1];
            vv.w = stw[prl * 2 + 1][cc + 1];
            *(float4*)&whbase[prl * 128 + cc * 2] = vv;
        }
    }
    // --- k/v fp16 writeout: [s][h][j][c], rows padded with zeros to 720 ---
    #pragma unroll
    for (int pass = 0; pass < 2; pass++) {
        const float* stx = pass ? &stv[0][0] : &stk[0][0];
        __half* gdst = pass ? g_vh : g_kh;
        #pragma unroll
        for (int o2 = tid; o2 < 1024; o2 += 256) {
            int cp = o2 & 7;          // c-pair 0..7
            int nl = (o2 >> 3) & 31;  // local row
            int hh = o2 >> 8;         // head 0..3
            int n = n0 + nl;
            if (n < 720) {
                float a = stx[nl * DD + hh * 16 + cp * 2];
                float b = stx[nl * DD + hh * 16 + cp * 2 + 1];
                *(__half2*)&gdst[(size_t)((s * 4 + hh) * 720 + n) * 16 + cp * 2] =
                    __floats2half2_rn(a, b);
            }
        }
    }
}

// ============================================================
// Kernel D: GAT. grid (48,45), block 256. No-max exp2 softmax;
// dual-branch lrelu via add.f32x2; j-paired f32x2 PV. (unchanged)
// ============================================================
__global__ __launch_bounds__(256) void gat_kernel() {
    __shared__ float p[16][720];
    __shared__ float red[8][16];
    __shared__ float rowsum[16];

    int s = blockIdx.x, t = blockIdx.y;
    int i0 = t * 16;
    int tid = threadIdx.x, lane = tid & 31, w = tid >> 5;
    const unsigned* __restrict__ cm = g_cmask + t * NS;
    const float* __restrict__ wh2 = g_Wh2 + s * NS;

    unsigned long long whb[16];
    #pragma unroll
    for (int ti = 0; ti < 16; ti++) {
        int i = min(i0 + ti, NS - 1);
        float v = g_Wh1[s * NS + i];
        whb[ti] = pack2(v, 0.2f * v);
    }

    float lsum[16];
    #pragma unroll
    for (int ti = 0; ti < 16; ti++) lsum[ti] = 0.f;
    for (int j = tid; j < 720; j += 256) {
        bool in = j < NS;
        float w2 = in ? wh2[j] : 0.f;
        unsigned mk = in ? cm[j] : 0u;
        unsigned long long w2p = pack2(w2, 0.2f * w2);
        #pragma unroll
        for (int ti = 0; ti < 16; ti++) {
            float lo, hi;
            unpack2(add2(whb[ti], w2p), lo, hi);
            float arg = fmaxf(lo, hi);
            float pe = ((mk >> ti) & 1u) ? ex2f(arg) : 0.0f;
            p[ti][j] = pe;
            lsum[ti] += pe;
        }
    }
    #pragma unroll
    for (int ti = 0; ti < 16; ti++)
        #pragma unroll
        for (int off = 16; off; off >>= 1)
            lsum[ti] += __shfl_xor_sync(0xffffffffu, lsum[ti], off);
    if (lane == 0) {
        #pragma unroll
        for (int ti = 0; ti < 16; ti++) red[w][ti] = lsum[ti];
    }
    __syncthreads();
    if (tid < 16) {
        float ss = red[0][tid];
        #pragma unroll
        for (int ww = 1; ww < 8; ww++) ss += red[ww][tid];
        rowsum[tid] = ss;
    }
    __syncthreads();

    int c = tid & 63, g = tid >> 6;
    unsigned long long acc2[16];
    #pragma unroll
    for (int ti = 0; ti < 16; ti++) acc2[ti] = 0ull;
    const unsigned long long* __restrict__ Whp2 =
        (const unsigned long long*)(g_Whp + (size_t)s * 360 * 128);
    for (int j0 = g * 8; j0 < 720; j0 += 32) {
        int pr = j0 >> 1;
        unsigned long long w0 = Whp2[(pr + 0) * 64 + c];
        unsigned long long w1 = Whp2[(pr + 1) * 64 + c];
        unsigned long long w2 = Whp2[(pr + 2) * 64 + c];
        unsigned long long w3 = Whp2[(pr + 3) * 64 + c];
        #pragma unroll
        for (int ti = 0; ti < 16; ti++) {
            ulonglong2 pa = *(const ulonglong2*)&p[ti][j0];
            ulonglong2 pb = *(const ulonglong2*)&p[ti][j0 + 4];
            acc2[ti] = ffma2(pa.x, w0, acc2[ti]);
            acc2[ti] = ffma2(pa.y, w1, acc2[ti]);
            acc2[ti] = ffma2(pb.x, w2, acc2[ti]);
            acc2[ti] = ffma2(pb.y, w3, acc2[ti]);
        }
    }
    float acc[16];
    #pragma unroll
    for (int ti = 0; ti < 16; ti++) {
        float lo, hi;
        unpack2(acc2[ti], lo, hi);
        acc[ti] = lo + hi;
    }
    __syncthreads();

    float* partial = &p[0][0];
    #pragma unroll
    for (int ti = 0; ti < 16; ti++) partial[(g * 16 + ti) * 64 + c] = acc[ti];
    __syncthreads();

    if (g == 0) {
        #pragma unroll
        for (int ti = 0; ti < 16; ti++) {
            int i = i0 + ti;
            if (i >= NS) continue;
            float v = (partial[ti * 64 + c] + partial[(16 + ti) * 64 + c] +
                       partial[(32 + ti) * 64 + c] + partial[(48 + ti) * 64 + c]) / rowsum[ti];
            v = v > 0.f ? v : expm1f(v);
            g_cat[(size_t)(s * NS + i) * 2 * DD + c] = v;
        }
    }
}

// ============================================================
// Kernel E: MHA via fp16 tensor cores. Register exp + DIRECT half
// accumulator store (no fp32 score round-trip). Exact l-4 pad comp.
// grid (48, 45, 4), block 128 (4 warps).
// ============================================================
__global__ __launch_bounds__(128) void mha_kernel() {
    __shared__ __align__(32) __half qh[256];
    __shared__ __align__(32) __half ph[4][256];
    __shared__ __align__(16) __half ring[4][4][2][256];   // [warp][stage][k/v][16x16]

    int s = blockIdx.x, i0 = blockIdx.y * 16, h = blockIdx.z;
    int tid = threadIdx.x, lane = tid & 31, w = tid >> 5;

    // stage q tile as fp16, pre-scaled into exp2 domain
    for (int idx = tid; idx < 256; idx += 128) {
        int r = idx >> 4, c = idx & 15;
        int iq = min(i0 + r, NS - 1);
        float v = g_q[(size_t)(s * NS + iq) * DD + h * 16 + c] * (0.25f * LOG2E);
        qh[idx] = __float2half(v);
    }
    __syncthreads();

    wmma::fragment<wmma::matrix_a, 16, 16, 16, __half, wmma::row_major> qa;
    wmma::load_matrix_sync(qa, qh, 16);
    wmma::fragment<wmma::matrix_b, 16, 16, 16, __half, wmma::row_major> bones;
    wmma::fill_fragment(bones, __float2half(1.0f));
    wmma::fragment<wmma::accumulator, 16, 16, 16, float> ofrag, lfrag;
    wmma::fill_fragment(ofrag, 0.0f);
    wmma::fill_fragment(lfrag, 0.0f);

    const __half* kg = g_kh + (size_t)(s * 4 + h) * 720 * 16;
    const __half* vg = g_vh + (size_t)(s * 4 + h) * 720 * 16;

    // prologue: fill 3 stages (chunks w, w+4, w+8 all < 45)
    #pragma unroll
    for (int st = 0; st < 3; st++) {
        int ch = w + st * 4;
        unsigned dk = (unsigned)__cvta_generic_to_shared(&ring[w][st][0][0]) + lane * 16;
        unsigned dv = (unsigned)__cvta_generic_to_shared(&ring[w][st][1][0]) + lane * 16;
        cp_async16(dk, (const char*)(kg + ch * 256) + lane * 16);
        cp_async16(dv, (const char*)(vg + ch * 256) + lane * 16);
        asm volatile("cp.async.commit_group;");
    }

    int nch = (48 - w) / 4;   // 12,11,11,11 chunks for warps 0..3
    for (int i = 0; i < nch; i++) {
        asm volatile("cp.async.wait_group 2;");
        int st = i & 3;

        // QK: scores(16q x 16j) = q(16x16) x k^T
        wmma::fragment<wmma::matrix_b, 16, 16, 16, __half, wmma::col_major> kb;
        wmma::load_matrix_sync(kb, &ring[w][st][0][0], 16);
        wmma::fragment<wmma::accumulator, 16, 16, 16, float> cfrag;
        wmma::fill_fragment(cfrag, 0.0f);
        wmma::mma_sync(cfrag, qa, kb, cfrag);

        // exp2 in registers, convert to half acc frag (same coord map), store once
        wmma::fragment<wmma::accumulator, 16, 16, 16, __half> hacc;
        #pragma unroll
        for (int e = 0; e < cfrag.num_elements; e++)
            hacc.x[e] = __float2half(ex2f(cfrag.x[e]));
        wmma::store_matrix_sync(&ph[w][0], hacc, 16, wmma::mem_row_major);
        __syncwarp();

        // PV + l accumulation (p x ones)
        wmma::fragment<wmma::matrix_a, 16, 16, 16, __half, wmma::row_major> pa;
        wmma::load_matrix_sync(pa, &ph[w][0], 16);
        wmma::fragment<wmma::matrix_b, 16, 16, 16, __half, wmma::row_major> vb;
        wmma::load_matrix_sync(vb, &ring[w][st][1][0], 16);
        wmma::mma_sync(ofrag, pa, vb, ofrag);
        wmma::mma_sync(lfrag, pa, bones, lfrag);

        // refill stage (i+3)%4 with chunk w+(i+3)*4
        int chn = w + (i + 3) * 4;
        if (chn < 45) {
            int stn = (i + 3) & 3;
            unsigned dk = (unsigned)__cvta_generic_to_shared(&ring[w][stn][0][0]) + lane * 16;
            unsigned dv = (unsigned)__cvta_generic_to_shared(&ring[w][stn][1][0]) + lane * 16;
            cp_async16(dk, (const char*)(kg + chn * 256) + lane * 16);
            cp_async16(dv, (const char*)(vg + chn * 256) + lane * 16);
        }
        asm volatile("cp.async.commit_group;");
    }
    asm volatile("cp.async.wait_group 0;");

    // epilogue overlaid on the (now dead) ring: per warp 1024 floats available
    float* osmw = (float*)&ring[w][0][0][0];        // 256 floats
    float* lsmw = osmw + 256;                       // 256 floats
    wmma::store_matrix_sync(osmw, ofrag, 16, wmma::mem_row_major);
    wmma::store_matrix_sync(lsmw, lfrag, 16, wmma::mem_row_major);
    __syncthreads();

    const float* fb = (const float*)&ring[0][0][0][0];   // warp stride = 1024 floats
    for (int idx = tid; idx < 256; idx += 128) {
        int r = idx >> 4, c = idx & 15;
        float o = fb[idx] + fb[1024 + idx] + fb[2048 + idx] + fb[3072 + idx];
        float l = fb[256 + r * 16] + fb[1280 + r * 16] +
                  fb[2304 + r * 16] + fb[3328 + r * 16] - 4.0f;  // exact pad compensation
        int i = i0 + r;
        if (i < NS)
            g_cat[(size_t)(s * NS + i) * 2 * DD + DD + h * 16 + c] = o / l;
    }
}

// ============================================================
// Kernel F: final projection, 16 rows/block, 4-way k-split, f32x2.
// ============================================================
__global__ __launch_bounds__(256) void final_kernel(const float* __restrict__ Wp,
                                                    float* __restrict__ out) {
    __shared__ float cs[16][2 * DD];
    __shared__ float pa[4][16][64];
    int s = blockIdx.x;
    int n0 = blockIdx.y * 16;
    int tid = threadIdx.x;

    #pragma unroll
    for (int half = 0; half < 2; half++) {
        int idx = half * 256 + tid;
        int r = idx >> 5, k4 = (idx & 31) * 4;
        int nn = min(n0 + r, NS - 1);
        *(float4*)&cs[r][k4] = *(const float4*)&g_cat[(size_t)(s * NS + nn) * 2 * DD + k4];
    }
    __syncthreads();

    int c = tid & 63, kg = tid >> 6;
    unsigned long long acc2[16];
    #pragma unroll
    for (int r = 0; r < 16; r++) acc2[r] = 0ull;
    for (int k0 = kg * 32; k0 < kg * 32 + 32; k0 += 2) {
        const float* w0 = (k0 < 64) ? (Wp + k0 * DD) : (g_Wc + (k0 - 64) * DD);
        unsigned long long wv = pack2(w0[c], w0[DD + c]);
        #pragma unroll
        for (int r = 0; r < 16; r++) {
            unsigned long long cv = *(const unsigned long long*)&cs[r][k0];
            acc2[r] = ffma2(cv, wv, acc2[r]);
        }
    }
    #pragma unroll
    for (int r = 0; r < 16; r++) {
        float lo, hi;
        unpack2(acc2[r], lo, hi);
        pa[kg][r][c] = lo + hi;
    }
    __syncthreads();

    if (kg == 0) {
        #pragma unroll
        for (int r = 0; r < 16; r++) {
            int n = n0 + r;
            if (n < NS)
                out[(size_t)(s * NS + n) * DD + c] =
                    pa[0][r][c] + pa[1][r][c] + pa[2][r][c] + pa[3][r][c] + g_bc[c];
        }
    }
}

// ============================================================
extern "C" void kernel_launch(void* const* d_in, const int* in_sizes, int n_in,
                              void* d_out, int out_size) {
    const float* x      = (const float*)d_in[0];
    const int*   adj    = (const int*)d_in[1];
    const int*   ind    = (const int*)d_in[2];
    const int*   outd   = (const int*)d_in[3];
    const float* in_emb = (const float*)d_in[4];
    const float* out_emb= (const float*)d_in[5];
    const float* W      = (const float*)d_in[6];
    const float* a1     = (const float*)d_in[7];
    const float* a2     = (const float*)d_in[8];
    const float* Wq     = (const float*)d_in[9];
    const float* bq     = (const float*)d_in[10];
    const float* Wk     = (const float*)d_in[11];
    const float* bk     = (const float*)d_in[12];
    const float* Wv     = (const float*)d_in[13];
    const float* bv     = (const float*)d_in[14];
    const float* Wo     = (const float*)d_in[15];
    const float* bo     = (const float*)d_in[16];
    const float* Wp     = (const float*)d_in[17];
    const float* bp     = (const float*)d_in[18];
    float* out = (float*)d_out;

    pre_kernel<<<229, 256>>>(adj, in_emb, out_emb, ind, outd, W, a1, a2, Wo, bo, Wp, bp);
    proj_kernel<<<dim3(NSAMP, (NS + BROWS - 1) / BROWS), 256>>>(x, W, Wq, bq, Wk, bk, Wv, bv);
    gat_kernel<<<dim3(NSAMP, NTILE), 256>>>();
    mha_kernel<<<dim3(NSAMP, NTILE, 4), 128>>>();
    final_kernel<<<dim3(NSAMP, NTILE), 256>>>(Wp, out);
}

// round 16
// speedup vs baseline: 1.8302x; 1.1946x over previous
#include <cuda_runtime.h>
#include <cuda_fp16.h>
#include <mma.h>
#include <math.h>

using namespace nvcuda;

#define NS 716
#define DD 64
#define NSAMP 48
#define NTILE 45            // ceil(716/16)
#define FINF 3.402823466e38f
#define LOG2E 1.4426950408889634f

// ---- scratch (device globals; no allocation) ----
__device__ float g_emb[NS * DD];
__device__ __half g_whh[NSAMP * 720 * 64];        // fp16 Wh [s][j][c], rows 716..719 zero
__device__ float g_Wh1[NSAMP * NS];               // pre-scaled by log2e
__device__ float g_Wh2[NSAMP * NS];               // pre-scaled by log2e
__device__ float g_q[NSAMP * NS * DD];
__device__ __half g_kh[NSAMP * 4 * 720 * 16];     // fp16 [s][h][j][c], rows 716..719 zero
__device__ __half g_vh[NSAMP * 4 * 720 * 16];
__device__ float g_cat[NSAMP * NS * 2 * DD];
__device__ unsigned g_cmask[NTILE * NS];
__device__ float g_wa1[DD];
__device__ float g_wa2[DD];
__device__ float g_Wc[DD * DD];   // Wo @ Wp[64:,:]
__device__ float g_bc[DD];        // bo @ Wp[64:,:] + bp

// ---- packed f32x2 helpers (sm_103a) ----
__device__ __forceinline__ unsigned long long pack2(float lo, float hi) {
    unsigned long long r;
    asm("mov.b64 %0, {%1, %2};" : "=l"(r) : "f"(lo), "f"(hi));
    return r;
}
__device__ __forceinline__ void unpack2(unsigned long long v, float& lo, float& hi) {
    asm("mov.b64 {%0, %1}, %2;" : "=f"(lo), "=f"(hi) : "l"(v));
}
__device__ __forceinline__ unsigned long long ffma2(unsigned long long a,
                                                    unsigned long long b,
                                                    unsigned long long c) {
    unsigned long long d;
    asm("fma.rn.f32x2 %0, %1, %2, %3;" : "=l"(d) : "l"(a), "l"(b), "l"(c));
    return d;
}
__device__ __forceinline__ unsigned long long add2(unsigned long long a,
                                                   unsigned long long b) {
    unsigned long long d;
    asm("add.rn.f32x2 %0, %1, %2;" : "=l"(d) : "l"(a), "l"(b));
    return d;
}
__device__ __forceinline__ float ex2f(float x) {
    float y;
    asm("ex2.approx.ftz.f32 %0, %1;" : "=f"(y) : "f"(x));
    return y;
}
__device__ __forceinline__ void cp_async16(unsigned sa, const void* g) {
    asm volatile("cp.async.cg.shared.global [%0], [%1], 16;" :: "r"(sa), "l"(g));
}

// ============================================================
// Kernel PRE: adjacency pack + embedding gather + weight prep
// grid 181 x 256
// ============================================================
__global__ void pre_kernel(const int* __restrict__ adj,
                           const float* __restrict__ in_emb,
                           const float* __restrict__ out_emb,
                           const int* __restrict__ ind,
                           const int* __restrict__ outd,
                           const float* __restrict__ W,
                           const float* __restrict__ a1, const float* __restrict__ a2,
                           const float* __restrict__ Wo, const float* __restrict__ bo,
                           const float* __restrict__ Wp, const float* __restrict__ bp) {
    int b = blockIdx.x, tid = threadIdx.x;
    if (b < 135) {
        int t = b / 3;
        int j = (b % 3) * 256 + tid;
        if (j < NS) {
            unsigned w = 0;
            #pragma unroll
            for (int ti = 0; ti < 16; ti++) {
                int i = t * 16 + ti;
                if (i < NS && adj[i * NS + j] != 0) w |= (1u << ti);
            }
            g_cmask[t * NS + j] = w;
        }
    } else if (b < 180) {
        int idx = (b - 135) * 256 + tid;
        if (idx < NS * 16) {
            int n = idx >> 4;
            int c4 = (idx & 15) * 4;
            float4 a = *(const float4*)&in_emb[ind[n] * DD + c4];
            float4 bb = *(const float4*)&out_emb[outd[n] * DD + c4];
            float4 r = {a.x + bb.x, a.y + bb.y, a.z + bb.z, a.w + bb.w};
            *(float4*)&g_emb[n * DD + c4] = r;
        }
    } else {
        if (tid < DD) {
            float s1 = 0.f, s2 = 0.f;
            #pragma unroll 8
            for (int c = 0; c < DD; c++) {
                float w = W[tid * DD + c];
                s1 = fmaf(w, a1[c], s1);
                s2 = fmaf(w, a2[c], s2);
            }
            g_wa1[tid] = s1 * LOG2E; g_wa2[tid] = s2 * LOG2E;
            float bsum = bp[tid];
            #pragma unroll 8
            for (int m = 0; m < DD; m++) bsum = fmaf(bo[m], Wp[(DD + m) * DD + tid], bsum);
            g_bc[tid] = bsum;
        }
        for (int o = tid; o < DD * DD; o += 256) {
            int k = o >> 6, c = o & 63;
            float acc = 0.f;
            #pragma unroll 8
            for (int m = 0; m < DD; m++)
                acc = fmaf(Wo[k * DD + m], Wp[(DD + m) * DD + c], acc);
            g_Wc[o] = acc;
        }
    }
}

// ============================================================
// Kernel B: fused projections + Wh1/Wh2. f32x2 inner; smem-staged
// coalesced writeout (whh fp16, k/v fp16, q fp32). grid (48, 23), block 256.
// ============================================================
#define BROWS 32
__global__ __launch_bounds__(256) void proj_kernel(
    const float* __restrict__ x,
    const float* __restrict__ W,  const float* __restrict__ Wq, const float* __restrict__ bq,
    const float* __restrict__ Wk, const float* __restrict__ bk,
    const float* __restrict__ Wv, const float* __restrict__ bv) {
    __shared__ float xs[BROWS][DD];
    __shared__ float ys[BROWS][DD];
    __shared__ float stw[BROWS][DD];
    __shared__ float stk[BROWS][DD];
    __shared__ float stv[BROWS][DD];
    int s = blockIdx.x;
    int n0 = blockIdx.y * BROWS;
    int tid = threadIdx.x, lane = tid & 31, w = tid >> 5;

    #pragma unroll
    for (int half = 0; half < 2; half++) {
        int idx = half * 256 + tid;
        int r = idx >> 4, k4 = (idx & 15) * 4;
        int nn = min(n0 + r, NS - 1);
        float4 xv = *(const float4*)&x[(size_t)(s * NS + nn) * DD + k4];
        float4 ev = *(const float4*)&g_emb[nn * DD + k4];
        *(float4*)&xs[r][k4] = xv;
        float4 yv = {xv.x + ev.x, xv.y + ev.y, xv.z + ev.z, xv.w + ev.w};
        *(float4*)&ys[r][k4] = yv;
    }
    __syncthreads();

    // Wh1/Wh2 (log2e-scaled via g_wa1/g_wa2)
    {
        float wa10 = g_wa1[lane], wa11 = g_wa1[32 + lane];
        float wa20 = g_wa2[lane], wa21 = g_wa2[32 + lane];
        #pragma unroll
        for (int rr = 0; rr < 4; rr++) {
            int r = w * 4 + rr, n = n0 + r;
            float x0 = xs[r][lane], x1 = xs[r][32 + lane];
            float s1 = x0 * wa10 + x1 * wa11;
            float s2 = x0 * wa20 + x1 * wa21;
            #pragma unroll
            for (int off = 16; off; off >>= 1) {
                s1 += __shfl_xor_sync(0xffffffffu, s1, off);
                s2 += __shfl_xor_sync(0xffffffffu, s2, off);
            }
            if (lane == 0 && n < NS) {
                g_Wh1[s * NS + n] = s1;
                g_Wh2[s * NS + n] = s2;
            }
        }
    }

    int m = tid >> 6, c = tid & 63;
    const float* wp = (m == 0) ? W : (m == 1) ? Wq : (m == 2) ? Wk : Wv;
    float bias = 0.f;
    if (m == 1) bias = bq[c]; else if (m == 2) bias = bk[c]; else if (m == 3) bias = bv[c];

    unsigned long long wcol2[32];
    #pragma unroll
    for (int k2 = 0; k2 < 32; k2++)
        wcol2[k2] = pack2(wp[(2 * k2) * DD + c], wp[(2 * k2 + 1) * DD + c]);

    float* st = (m == 0) ? &stw[0][0] : (m == 2) ? &stk[0][0] : &stv[0][0];

    for (int r = 0; r < BROWS; r++) {
        int n = n0 + r;
        float acc = 0.f;
        if (n < NS) {
            const float* src = (m == 0) ? xs[r] : ys[r];
            unsigned long long acc2 = pack2(bias, 0.f);
            #pragma unroll
            for (int k2 = 0; k2 < 32; k2 += 2) {
                ulonglong2 sv = *(const ulonglong2*)&src[k2 * 2];
                acc2 = ffma2(sv.x, wcol2[k2], acc2);
                acc2 = ffma2(sv.y, wcol2[k2 + 1], acc2);
            }
            float lo, hi;
            unpack2(acc2, lo, hi);
            acc = lo + hi;
        }
        if (m == 1) {
            if (n < NS) g_q[(size_t)(s * NS + n) * DD + c] = acc;
        } else {
            st[r * DD + c] = acc;     // zero for n >= NS
        }
    }
    __syncthreads();

    // --- whh fp16 writeout: [s][j][c], rows >= NS get zeros from stw ---
    #pragma unroll
    for (int o2 = tid; o2 < 1024; o2 += 256) {
        int nl = o2 >> 5, cp = o2 & 31;
        int n = n0 + nl;
        if (n < 720) {
            float a = stw[nl][cp * 2];
            float b = stw[nl][cp * 2 + 1];
            *(__half2*)&g_whh[(size_t)(s * 720 + n) * 64 + cp * 2] = __floats2half2_rn(a, b);
        }
    }
    // --- k/v fp16 writeout: [s][h][j][c], rows padded with zeros to 720 ---
    #pragma unroll
    for (int pass = 0; pass < 2; pass++) {
        const float* stx = pass ? &stv[0][0] : &stk[0][0];
        __half* gdst = pass ? g_vh : g_kh;
        #pragma unroll
        for (int o2 = tid; o2 < 1024; o2 += 256) {
            int cp = o2 & 7;          // c-pair 0..7
            int nl = (o2 >> 3) & 31;  // local row
            int hh = o2 >> 8;         // head 0..3
            int n = n0 + nl;
            if (n < 720) {
                float a = stx[nl * DD + hh * 16 + cp * 2];
                float b = stx[nl * DD + hh * 16 + cp * 2 + 1];
                *(__half2*)&gdst[(size_t)((s * 4 + hh) * 720 + n) * 16 + cp * 2] =
                    __floats2half2_rn(a, b);
            }
        }
    }
}

// ============================================================
// Kernel D: GAT with fp16 tensor-core PV + mma rowsum.
// grid (48,45), block 256 (8 warps = 4 n-tiles x 2 j-halves).
// ============================================================
__global__ __launch_bounds__(256) void gat_kernel() {
    __shared__ __align__(32) __half ph[16 * 720];   // 23040 B; overlaid by o/l after PV

    int s = blockIdx.x, t = blockIdx.y;
    int i0 = t * 16;
    int tid = threadIdx.x, w = tid >> 5;
    const unsigned* __restrict__ cm = g_cmask + t * NS;
    const float* __restrict__ wh2 = g_Wh2 + s * NS;

    unsigned long long whb[16];
    #pragma unroll
    for (int ti = 0; ti < 16; ti++) {
        int i = min(i0 + ti, NS - 1);
        float v = g_Wh1[s * NS + i];
        whb[ti] = pack2(v, 0.2f * v);
    }

    // exp2(lrelu) pass, masked, fp16 p (no max subtraction: args <= ~15)
    for (int j = tid; j < 720; j += 256) {
        bool in = j < NS;
        float w2 = in ? wh2[j] : 0.f;
        unsigned mk = in ? cm[j] : 0u;
        unsigned long long w2p = pack2(w2, 0.2f * w2);
        #pragma unroll
        for (int ti = 0; ti < 16; ti++) {
            float lo, hi;
            unpack2(add2(whb[ti], w2p), lo, hi);
            float arg = fmaxf(lo, hi);
            float pe = ((mk >> ti) & 1u) ? ex2f(arg) : 0.0f;
            ph[ti * 720 + j] = __float2half(pe);
        }
    }
    __syncthreads();

    // PV via wmma: warp w -> n-tile (w&3), j-half (w>>2)
    int nt = w & 3, jh = w >> 2;
    wmma::fragment<wmma::accumulator, 16, 16, 16, float> ofrag, lfrag;
    wmma::fill_fragment(ofrag, 0.0f);
    wmma::fill_fragment(lfrag, 0.0f);
    wmma::fragment<wmma::matrix_b, 16, 16, 16, __half, wmma::row_major> bones;
    wmma::fill_fragment(bones, __float2half(1.0f));

    const __half* whh = g_whh + (size_t)s * 720 * 64;
    int c0 = jh ? 23 : 0, c1 = jh ? 45 : 23;
    for (int ch = c0; ch < c1; ch++) {
        wmma::fragment<wmma::matrix_a, 16, 16, 16, __half, wmma::row_major> pa;
        wmma::load_matrix_sync(pa, ph + ch * 16, 720);
        wmma::fragment<wmma::matrix_b, 16, 16, 16, __half, wmma::row_major> vb;
        wmma::load_matrix_sync(vb, whh + (size_t)ch * 16 * 64 + nt * 16, 64);
        wmma::mma_sync(ofrag, pa, vb, ofrag);
        if (nt == 0) wmma::mma_sync(lfrag, pa, bones, lfrag);
    }
    __syncthreads();   // all ph reads done before overlay

    float* osm = (float*)ph;            // [8][256]
    float* lsm = osm + 2048;            // [2][256]
    wmma::store_matrix_sync(osm + w * 256, ofrag, 16, wmma::mem_row_major);
    if (nt == 0) wmma::store_matrix_sync(lsm + jh * 256, lfrag, 16, wmma::mem_row_major);
    __syncthreads();

    // combine halves, divide, ELU, write
    #pragma unroll
    for (int e = 0; e < 4; e++) {
        int idx = e * 256 + tid;
        int r = idx >> 6, c = idx & 63;
        int nt2 = c >> 4, cc = c & 15;
        float o = osm[nt2 * 256 + r * 16 + cc] + osm[(4 + nt2) * 256 + r * 16 + cc];
        float l = lsm[r * 16] + lsm[256 + r * 16];
        float v = o / l;
        v = v > 0.f ? v : expm1f(v);
        int i = i0 + r;
        if (i < NS)
            g_cat[(size_t)(s * NS + i) * 2 * DD + c] = v;
    }
}

// ============================================================
// Kernel E: MHA via fp16 tensor cores. Register exp + direct half
// accumulator store. Exact l-4 pad comp. grid (48, 45, 4), block 128.
// ============================================================
__global__ __launch_bounds__(128) void mha_kernel() {
    __shared__ __align__(32) __half qh[256];
    __shared__ __align__(32) __half ph[4][256];
    __shared__ __align__(16) __half ring[4][4][2][256];   // [warp][stage][k/v][16x16]

    int s = blockIdx.x, i0 = blockIdx.y * 16, h = blockIdx.z;
    int tid = threadIdx.x, lane = tid & 31, w = tid >> 5;

    for (int idx = tid; idx < 256; idx += 128) {
        int r = idx >> 4, c = idx & 15;
        int iq = min(i0 + r, NS - 1);
        float v = g_q[(size_t)(s * NS + iq) * DD + h * 16 + c] * (0.25f * LOG2E);
        qh[idx] = __float2half(v);
    }
    __syncthreads();

    wmma::fragment<wmma::matrix_a, 16, 16, 16, __half, wmma::row_major> qa;
    wmma::load_matrix_sync(qa, qh, 16);
    wmma::fragment<wmma::matrix_b, 16, 16, 16, __half, wmma::row_major> bones;
    wmma::fill_fragment(bones, __float2half(1.0f));
    wmma::fragment<wmma::accumulator, 16, 16, 16, float> ofrag, lfrag;
    wmma::fill_fragment(ofrag, 0.0f);
    wmma::fill_fragment(lfrag, 0.0f);

    const __half* kg = g_kh + (size_t)(s * 4 + h) * 720 * 16;
    const __half* vg = g_vh + (size_t)(s * 4 + h) * 720 * 16;

    #pragma unroll
    for (int st = 0; st < 3; st++) {
        int ch = w + st * 4;
        unsigned dk = (unsigned)__cvta_generic_to_shared(&ring[w][st][0][0]) + lane * 16;
        unsigned dv = (unsigned)__cvta_generic_to_shared(&ring[w][st][1][0]) + lane * 16;
        cp_async16(dk, (const char*)(kg + ch * 256) + lane * 16);
        cp_async16(dv, (const char*)(vg + ch * 256) + lane * 16);
        asm volatile("cp.async.commit_group;");
    }

    int nch = (48 - w) / 4;   // 12,11,11,11 chunks for warps 0..3
    for (int i = 0; i < nch; i++) {
        asm volatile("cp.async.wait_group 2;");
        int st = i & 3;

        wmma::fragment<wmma::matrix_b, 16, 16, 16, __half, wmma::col_major> kb;
        wmma::load_matrix_sync(kb, &ring[w][st][0][0], 16);
        wmma::fragment<wmma::accumulator, 16, 16, 16, float> cfrag;
        wmma::fill_fragment(cfrag, 0.0f);
        wmma::mma_sync(cfrag, qa, kb, cfrag);

        wmma::fragment<wmma::accumulator, 16, 16, 16, __half> hacc;
        #pragma unroll
        for (int e = 0; e < cfrag.num_elements; e++)
            hacc.x[e] = __float2half(ex2f(cfrag.x[e]));
        wmma::store_matrix_sync(&ph[w][0], hacc, 16, wmma::mem_row_major);
        __syncwarp();

        wmma::fragment<wmma::matrix_a, 16, 16, 16, __half, wmma::row_major> pa;
        wmma::load_matrix_sync(pa, &ph[w][0], 16);
        wmma::fragment<wmma::matrix_b, 16, 16, 16, __half, wmma::row_major> vb;
        wmma::load_matrix_sync(vb, &ring[w][st][1][0], 16);
        wmma::mma_sync(ofrag, pa, vb, ofrag);
        wmma::mma_sync(lfrag, pa, bones, lfrag);

        int chn = w + (i + 3) * 4;
        if (chn < 45) {
            int stn = (i + 3) & 3;
            unsigned dk = (unsigned)__cvta_generic_to_shared(&ring[w][stn][0][0]) + lane * 16;
            unsigned dv = (unsigned)__cvta_generic_to_shared(&ring[w][stn][1][0]) + lane * 16;
            cp_async16(dk, (const char*)(kg + chn * 256) + lane * 16);
            cp_async16(dv, (const char*)(vg + chn * 256) + lane * 16);
        }
        asm volatile("cp.async.commit_group;");
    }
    asm volatile("cp.async.wait_group 0;");

    float* osmw = (float*)&ring[w][0][0][0];
    float* lsmw = osmw + 256;
    wmma::store_matrix_sync(osmw, ofrag, 16, wmma::mem_row_major);
    wmma::store_matrix_sync(lsmw, lfrag, 16, wmma::mem_row_major);
    __syncthreads();

    const float* fb = (const float*)&ring[0][0][0][0];
    for (int idx = tid; idx < 256; idx += 128) {
        int r = idx >> 4, c = idx & 15;
        float o = fb[idx] + fb[1024 + idx] + fb[2048 + idx] + fb[3072 + idx];
        float l = fb[256 + r * 16] + fb[1280 + r * 16] +
                  fb[2304 + r * 16] + fb[3328 + r * 16] - 4.0f;
        int i = i0 + r;
        if (i < NS)
            g_cat[(size_t)(s * NS + i) * 2 * DD + DD + h * 16 + c] = o / l;
    }
}

// ============================================================
// Kernel F: final projection, 16 rows/block, 4-way k-split, f32x2.
// ============================================================
__global__ __launch_bounds__(256) void final_kernel(const float* __restrict__ Wp,
                                                    float* __restrict__ out) {
    __shared__ float cs[16][2 * DD];
    __shared__ float pa[4][16][64];
    int s = blockIdx.x;
    int n0 = blockIdx.y * 16;
    int tid = threadIdx.x;

    #pragma unroll
    for (int half = 0; half < 2; half++) {
        int idx = half * 256 + tid;
        int r = idx >> 5, k4 = (idx & 31) * 4;
        int nn = min(n0 + r, NS - 1);
        *(float4*)&cs[r][k4] = *(const float4*)&g_cat[(size_t)(s * NS + nn) * 2 * DD + k4];
    }
    __syncthreads();

    int c = tid & 63, kg = tid >> 6;
    unsigned long long acc2[16];
    #pragma unroll
    for (int r = 0; r < 16; r++) acc2[r] = 0ull;
    for (int k0 = kg * 32; k0 < kg * 32 + 32; k0 += 2) {
        const float* w0 = (k0 < 64) ? (Wp + k0 * DD) : (g_Wc + (k0 - 64) * DD);
        unsigned long long wv = pack2(w0[c], w0[DD + c]);
        #pragma unroll
        for (int r = 0; r < 16; r++) {
            unsigned long long cv = *(const unsigned long long*)&cs[r][k0];
            acc2[r] = ffma2(cv, wv, acc2[r]);
        }
    }
    #pragma unroll
    for (int r = 0; r < 16; r++) {
        float lo, hi;
        unpack2(acc2[r], lo, hi);
        pa[kg][r][c] = lo + hi;
    }
    __syncthreads();

    if (kg == 0) {
        #pragma unroll
        for (int r = 0; r < 16; r++) {
            int n = n0 + r;
            if (n < NS)
                out[(size_t)(s * NS + n) * DD + c] =
                    pa[0][r][c] + pa[1][r][c] + pa[2][r][c] + pa[3][r][c] + g_bc[c];
        }
    }
}

// ============================================================
extern "C" void kernel_launch(void* const* d_in, const int* in_sizes, int n_in,
                              void* d_out, int out_size) {
    const float* x      = (const float*)d_in[0];
    const int*   adj    = (const int*)d_in[1];
    const int*   ind    = (const int*)d_in[2];
    const int*   outd   = (const int*)d_in[3];
    const float* in_emb = (const float*)d_in[4];
    const float* out_emb= (const float*)d_in[5];
    const float* W      = (const float*)d_in[6];
    const float* a1     = (const float*)d_in[7];
    const float* a2     = (const float*)d_in[8];
    const float* Wq     = (const float*)d_in[9];
    const float* bq     = (const float*)d_in[10];
    const float* Wk     = (const float*)d_in[11];
    const float* bk     = (const float*)d_in[12];
    const float* Wv     = (const float*)d_in[13];
    const float* bv     = (const float*)d_in[14];
    const float* Wo     = (const float*)d_in[15];
    const float* bo     = (const float*)d_in[16];
    const float* Wp     = (const float*)d_in[17];
    const float* bp     = (const float*)d_in[18];
    float* out = (float*)d_out;

    pre_kernel<<<181, 256>>>(adj, in_emb, out_emb, ind, outd, W, a1, a2, Wo, bo, Wp, bp);
    proj_kernel<<<dim3(NSAMP, (NS + BROWS - 1) / BROWS), 256>>>(x, W, Wq, bq, Wk, bk, Wv, bv);
    gat_kernel<<<dim3(NSAMP, NTILE), 256>>>();
    mha_kernel<<<dim3(NSAMP, NTILE, 4), 128>>>();
    final_kernel<<<dim3(NSAMP, NTILE), 256>>>(Wp, out);
}